// round 10
// baseline (speedup 1.0000x reference)
#include <cuda_runtime.h>
#include <cuda_bf16.h>
#include <cuda_fp16.h>
#include <math.h>
#include <stdint.h>

// Problem constants
#define B_ 2
#define T_ 2048
#define C_ 1024
#define H_ 16
#define D_ 64
#define WIN_ 512
#define K_ 1024

// GEMM tiling: fp16 single-product, BK=16, 8-stage cp.async
#define SP 24                       // padded row stride (fp16 elems) = 48 B
#define TILE_B (128 * SP * 2)       // 6144 B per 128x16 tile
#define STAGE_B (2 * TILE_B)        // A, B = 12288 B
#define NSTAGE 8                    // power of 2 (ring mask)
#define GSMEM (NSTAGE * STAGE_B)    // 98304 B

// Attention smem (static): Qf[128]+Kf[64] fp16, Vh/Vl[64] bf16, stride ASP
#define ASP 72

// ---------------- scratch (allocation-free) ----------------
__device__ __half        g_Qf[B_*H_*T_*D_];
__device__ __half        g_Kf[B_*H_*T_*D_];
__device__ __nv_bfloat16 g_Vh[B_*H_*T_*D_], g_Vl[B_*H_*T_*D_];
__device__ __half        g_xf[B_*T_*C_];
__device__ __half        g_wqf[3*C_*C_];
__device__ __half        g_wpf[C_*C_];
__device__ __half        g_yf[B_*T_*C_];

__device__ __forceinline__ uint32_t smem_u32(const void* p) {
    uint32_t a;
    asm("{ .reg .u64 t; cvta.to.shared.u64 t, %1; cvt.u32.u64 %0, t; }"
        : "=r"(a) : "l"(p));
    return a;
}
#define LDMX4(r0, r1, r2, r3, addr)                                          \
    asm volatile("ldmatrix.sync.aligned.m8n8.x4.shared.b16 {%0,%1,%2,%3}, [%4];" \
        : "=r"(r0), "=r"(r1), "=r"(r2), "=r"(r3) : "r"(addr))
#define LDMX4T(r0, r1, r2, r3, addr)                                         \
    asm volatile("ldmatrix.sync.aligned.m8n8.x4.trans.shared.b16 {%0,%1,%2,%3}, [%4];" \
        : "=r"(r0), "=r"(r1), "=r"(r2), "=r"(r3) : "r"(addr))
// bf16 HMMA
#define MMA16816(c, a0, a1, a2, a3, b0, b1)                                  \
    asm volatile("mma.sync.aligned.m16n8k16.row.col.f32.bf16.bf16.f32 "      \
        "{%0,%1,%2,%3}, {%4,%5,%6,%7}, {%8,%9}, {%0,%1,%2,%3};"              \
        : "+f"((c)[0]), "+f"((c)[1]), "+f"((c)[2]), "+f"((c)[3])             \
        : "r"(a0), "r"(a1), "r"(a2), "r"(a3), "r"(b0), "r"(b1))
// fp16 HMMA
#define MMAH16816(c, a0, a1, a2, a3, b0, b1)                                 \
    asm volatile("mma.sync.aligned.m16n8k16.row.col.f32.f16.f16.f32 "        \
        "{%0,%1,%2,%3}, {%4,%5,%6,%7}, {%8,%9}, {%0,%1,%2,%3};"              \
        : "+f"((c)[0]), "+f"((c)[1]), "+f"((c)[2]), "+f"((c)[3])             \
        : "r"(a0), "r"(a1), "r"(a2), "r"(a3), "r"(b0), "r"(b1))
#define PACKBF2(r, lo, hi)                                                   \
    asm("cvt.rn.bf16x2.f32 %0, %1, %2;" : "=r"(r) : "f"(hi), "f"(lo))
#define CP16(dst, src)                                                       \
    asm volatile("cp.async.cg.shared.global [%0], [%1], 16;" :: "r"(dst), "l"(src))
#define CP_COMMIT() asm volatile("cp.async.commit_group;" ::: "memory")
#define CP_WAIT(n)  asm volatile("cp.async.wait_group %0;" :: "n"(n) : "memory")

// ---------------- convert fp32 -> fp16 ----------------
__global__ __launch_bounds__(256) void cvt_f16(
    const float* __restrict__ s, __half* __restrict__ d, int n4)
{
    int i = blockIdx.x * 256 + threadIdx.x;
    if (i >= n4) return;
    float4 v = ((const float4*)s)[i];
    __half2 h0 = __halves2half2(__float2half_rn(v.x), __float2half_rn(v.y));
    __half2 h1 = __halves2half2(__float2half_rn(v.z), __float2half_rn(v.w));
    ((__half2*)d)[2*i]   = h0;
    ((__half2*)d)[2*i+1] = h1;
}

// ---------------- fp16 single-product tensor-core GEMM --------------------
// D[m,n] = sum_k A[m,k]*W[n,k] + bias[n]  (single fp16 HMMA product)
// CTA 128x128, BK=16, 256 threads = 8 warps (4m x 2n), warp tile 32x64,
// 8-stage cp.async, ONE __syncthreads per K16, direct-from-fragment epilogue.
// MODE 0: q,k -> fp16; v -> bf16 hi/lo (scatter [B,H,T,d]).  MODE 1: fp32 out.
template <int MODE>
__global__ __launch_bounds__(256, 2) void gemm_f16_kernel(
    const __half* __restrict__ Af, const __half* __restrict__ Bf,
    const float* __restrict__ bias, float* __restrict__ Cout)
{
    extern __shared__ char smem[];
    const uint32_t sb = smem_u32(smem);
    const int tid = threadIdx.x;
    const int wid = tid >> 5;
    const int lane = tid & 31;
    const int warp_m = wid & 3;      // 4 x 32 rows
    const int warp_n = wid >> 2;     // 2 x 64 cols
    const int bn = blockIdx.x, bm = blockIdx.y;

    // cp.async: thread -> (tile ct, row); 2x 16B chunks per 32B row
    const int ct = tid >> 7;          // 0=A, 1=B
    const int crow = tid & 127;
    const __half* const csrc = (ct == 0)
        ? Af + (size_t)(bm * 128 + crow) * K_
        : Bf + (size_t)(bn * 128 + crow) * K_;
    const uint32_t cdst = sb + (uint32_t)(ct * TILE_B + crow * SP * 2);

    // ldmatrix per-lane byte offsets within a tile
    const uint32_t aoff = (uint32_t)(
        (warp_m * 32 + (lane & 7) + ((lane >> 3) & 1) * 8) * SP
        + (lane >> 4) * 8) * 2;
    const uint32_t boff = (uint32_t)(
        (warp_n * 64 + (lane & 7) + (lane >> 4) * 8) * SP
        + ((lane >> 3) & 1) * 8) * 2;

    float acc[2][8][4];
    #pragma unroll
    for (int i = 0; i < 2; i++)
        #pragma unroll
        for (int j = 0; j < 8; j++)
            #pragma unroll
            for (int c = 0; c < 4; c++) acc[i][j][c] = 0.f;

    const int NT = K_ / 16;   // 64

    #pragma unroll
    for (int st = 0; st < NSTAGE - 1; st++) {
        CP16(cdst + st * STAGE_B,      csrc + st * 16);
        CP16(cdst + st * STAGE_B + 16, csrc + st * 16 + 8);
        CP_COMMIT();
    }

    for (int it = 0; it < NT; ++it) {
        CP_WAIT(NSTAGE - 2);
        __syncthreads();
        const uint32_t tb = sb + (uint32_t)(it & (NSTAGE - 1)) * STAGE_B;

        if (it + NSTAGE - 1 < NT) {
            const uint32_t db = cdst + (uint32_t)((it + NSTAGE - 1) & (NSTAGE - 1)) * STAGE_B;
            CP16(db,      csrc + (it + NSTAGE - 1) * 16);
            CP16(db + 16, csrc + (it + NSTAGE - 1) * 16 + 8);
        }
        CP_COMMIT();

        uint32_t af[2][4];
        #pragma unroll
        for (int mf = 0; mf < 2; mf++) {
            const uint32_t ao = tb + aoff + (uint32_t)(mf * 16 * SP) * 2;
            LDMX4(af[mf][0], af[mf][1], af[mf][2], af[mf][3], ao);
        }
        #pragma unroll
        for (int nf2 = 0; nf2 < 4; nf2++) {
            uint32_t bf[4];
            const uint32_t bo = tb + TILE_B + boff + (uint32_t)(nf2 * 16 * SP) * 2;
            LDMX4(bf[0], bf[1], bf[2], bf[3], bo);
            #pragma unroll
            for (int mf = 0; mf < 2; mf++) {
                MMAH16816(acc[mf][nf2*2],   af[mf][0], af[mf][1], af[mf][2], af[mf][3],
                          bf[0], bf[1]);
                MMAH16816(acc[mf][nf2*2+1], af[mf][0], af[mf][1], af[mf][2], af[mf][3],
                          bf[2], bf[3]);
            }
        }
    }
    CP_WAIT(0);

    // ---- direct-from-fragment epilogue ----
    const int g = lane >> 2, tg = lane & 3;
    #pragma unroll
    for (int mf = 0; mf < 2; mf++) {
        #pragma unroll
        for (int nf = 0; nf < 8; nf++) {
            const int gc = bn * 128 + warp_n * 64 + nf * 8 + tg * 2;
            const float b0 = bias[gc], b1 = bias[gc + 1];
            const int r0 = bm * 128 + warp_m * 32 + mf * 16 + g;
            const float v0 = acc[mf][nf][0] + b0, v1 = acc[mf][nf][1] + b1;
            const float v2 = acc[mf][nf][2] + b0, v3 = acc[mf][nf][3] + b1;
            if (MODE == 0) {
                const int sel = gc >> 10;
                const int within = gc & 1023;
                const int h = within >> 6;
                const int dd = within & 63;
                #pragma unroll
                for (int rr = 0; rr < 2; rr++) {
                    const int m = r0 + rr * 8;
                    const int b = m >> 11, t = m & 2047;
                    const float y0 = rr ? v2 : v0, y1 = rr ? v3 : v1;
                    const size_t o = (((size_t)(b * H_ + h)) * T_ + t) * D_ + dd;
                    if (sel == 2) {
                        uint32_t hp, lp;
                        PACKBF2(hp, y0, y1);
                        const float e0 = y0 - __uint_as_float(hp << 16);
                        const float e1 = y1 - __uint_as_float(hp & 0xFFFF0000u);
                        PACKBF2(lp, e0, e1);
                        *(uint32_t*)(g_Vh + o) = hp;
                        *(uint32_t*)(g_Vl + o) = lp;
                    } else {
                        __half2 hv = __halves2half2(__float2half_rn(y0),
                                                    __float2half_rn(y1));
                        *(__half2*)((sel == 0 ? g_Qf : g_Kf) + o) = hv;
                    }
                }
            } else {
                #pragma unroll
                for (int rr = 0; rr < 2; rr++) {
                    const int m = r0 + rr * 8;
                    float2 y;
                    y.x = rr ? v2 : v0;
                    y.y = rr ? v3 : v1;
                    *(float2*)(Cout + (size_t)m * C_ + gc) = y;
                }
            }
        }
    }
}

// ---------------------------------------------------------------------------
// Polynomial softcap+exp, ONE MUFU per element.
// p ~ exp(30*tanh(raw/240))  (common scale e^30 dropped; cancels in softmax)
//   = exp2(raw*(d0 + d1*w + d2*w^2)), w = raw^2   (odd Taylor of tanh folded
//     with the 1/8 score scale and log2 e).  |raw| clamped to 60 (18 sigma);
//     poly err <= ~1e-5 on that range.
// ---------------------------------------------------------------------------
__device__ __forceinline__ float softp(float raw, bool valid) {
    const float r = fminf(fmaxf(raw, -60.0f), 60.0f);
    const float w = r * r;
    const float u = r * fmaf(fmaf(7.2473e-12f, w, -1.0436162e-6f), w,
                             0.18033688011f);
    float p;
    asm("ex2.approx.f32 %0, %1;" : "=f"(p) : "f"(u));
    return valid ? p : 0.0f;
}

// ---------------------------------------------------------------------------
// Attention: 128 q-rows/CTA, 8 warps, 64-key tiles.
// QK^T: single fp16 product.  PV: Ph*Vh + Ph*Vl + Pl*Vh (bf16 hi/lo).
// Epilogue writes y directly as fp16 (proj GEMM input).
// ---------------------------------------------------------------------------
__global__ __launch_bounds__(256, 2) void attn_kernel(const int* __restrict__ spl)
{
    __shared__ __half        Qf[128 * ASP];
    __shared__ __half        Kf[64 * ASP];
    __shared__ __nv_bfloat16 Vh[64 * ASP];
    __shared__ __nv_bfloat16 Vl[64 * ASP];

    const int tid = threadIdx.x;
    const int wid = tid >> 5;      // 0..7
    const int lane = tid & 31;
    const int q0 = blockIdx.x * 128;
    const int h = blockIdx.y;
    const int b = blockIdx.z;
    const size_t bh = (size_t)(b * H_ + h) * T_;
    const int P = spl[b];

    // load Q: 128 rows x 8 uint4
    for (int i = tid; i < 1024; i += 256) {
        const int r = i >> 3;
        const int c8 = i & 7;
        *(uint4*)(Qf + r * ASP + c8 * 8) =
            *(const uint4*)(g_Qf + (bh + q0 + r) * D_ + c8 * 8);
    }

    const int a_row = wid * 16 + (lane & 7) + ((lane >> 3) & 1) * 8;
    const int a_kg = (lane >> 4) * 8;
    const uint32_t qf_a = smem_u32(Qf + a_row * ASP + a_kg);
    const int k_row = (lane & 7) + (lane >> 4) * 8;
    const int k_col = ((lane >> 3) & 1) * 8;
    const uint32_t kf_a = smem_u32(Kf + k_row * ASP + k_col);
    const int v_row = ((lane >> 3) & 1) * 8 + (lane & 7);
    const int v_col = (lane >> 4) * 8;
    const uint32_t vh_a = smem_u32(Vh + v_row * ASP + v_col);
    const uint32_t vl_a = smem_u32(Vl + v_row * ASP + v_col);

    float o[8][4];
    #pragma unroll
    for (int i = 0; i < 8; i++)
        #pragma unroll
        for (int j = 0; j < 4; j++) o[i][j] = 0.f;
    float lsum0 = 0.f, lsum1 = 0.f;
    const int row0 = q0 + wid * 16 + (lane >> 2);

    for (int kt = 0; kt < T_ / 64; kt++) {
        const int k0 = kt * 64;
        const bool tv = (k0 < P) || ((k0 <= q0 + 127) && (k0 + 63 >= q0 - WIN_));
        if (!tv) continue;   // uniform across block

        __syncthreads();
        // K fp16 + V hi/lo bf16: 3 arrays x 64 rows x 8 uint4 = 1536
        for (int i = tid; i < 1536; i += 256) {
            const int arr = i >> 9;
            const int r = (i >> 3) & 63;
            const int c8 = i & 7;
            const size_t src_o = (bh + k0 + r) * D_ + c8 * 8;
            if (arr == 0)
                *(uint4*)(Kf + r * ASP + c8 * 8) = *(const uint4*)(g_Kf + src_o);
            else if (arr == 1)
                *(uint4*)(Vh + r * ASP + c8 * 8) = *(const uint4*)(g_Vh + src_o);
            else
                *(uint4*)(Vl + r * ASP + c8 * 8) = *(const uint4*)(g_Vl + src_o);
        }
        __syncthreads();

        // ---- QK^T (single fp16 product) -> s[8][4] ----
        float s[8][4];
        #pragma unroll
        for (int i = 0; i < 8; i++)
            #pragma unroll
            for (int j = 0; j < 4; j++) s[i][j] = 0.f;

        #pragma unroll
        for (int kk4 = 0; kk4 < 4; kk4++) {
            uint32_t qa[4];
            LDMX4(qa[0], qa[1], qa[2], qa[3], qf_a + kk4 * 32);
            #pragma unroll
            for (int nf2 = 0; nf2 < 4; nf2++) {
                uint32_t kb[4];
                LDMX4(kb[0], kb[1], kb[2], kb[3],
                      kf_a + (uint32_t)(nf2 * 16 * ASP) * 2 + kk4 * 32);
                MMAH16816(s[nf2*2],   qa[0], qa[1], qa[2], qa[3], kb[0], kb[1]);
                MMAH16816(s[nf2*2+1], qa[0], qa[1], qa[2], qa[3], kb[2], kb[3]);
            }
        }

        // ---- softcap/mask/exp + C->A repack + PV (bf16 3-product) ----
        #pragma unroll
        for (int kc = 0; kc < 4; kc++) {
            uint32_t pah[4], pal[4];
            #pragma unroll
            for (int j = 0; j < 2; j++) {
                const int nf = kc * 2 + j;
                const int cb = k0 + nf * 8 + (lane & 3) * 2;
                const bool va0 = ((cb     <= row0)     && (row0     - cb     <= WIN_)) || (cb     < P);
                const bool va1 = ((cb + 1 <= row0)     && (row0     - cb - 1 <= WIN_)) || (cb + 1 < P);
                const bool va2 = ((cb     <= row0 + 8) && (row0 + 8 - cb     <= WIN_)) || (cb     < P);
                const bool va3 = ((cb + 1 <= row0 + 8) && (row0 + 8 - cb - 1 <= WIN_)) || (cb + 1 < P);
                const float p0 = softp(s[nf][0], va0);
                const float p1 = softp(s[nf][1], va1);
                const float p2 = softp(s[nf][2], va2);
                const float p3 = softp(s[nf][3], va3);
                lsum0 += p0 + p1;
                lsum1 += p2 + p3;
                uint32_t h01, h23;
                PACKBF2(h01, p0, p1);
                PACKBF2(h23, p2, p3);
                pah[j*2]   = h01;
                pah[j*2+1] = h23;
                const float r0 = p0 - __uint_as_float(h01 << 16);
                const float r1 = p1 - __uint_as_float(h01 & 0xFFFF0000u);
                const float r2 = p2 - __uint_as_float(h23 << 16);
                const float r3 = p3 - __uint_as_float(h23 & 0xFFFF0000u);
                uint32_t l01, l23;
                PACKBF2(l01, r0, r1);
                PACKBF2(l23, r2, r3);
                pal[j*2]   = l01;
                pal[j*2+1] = l23;
            }
            #pragma unroll
            for (int nf2 = 0; nf2 < 4; nf2++) {
                uint32_t vb_h[4], vb_l[4];
                const uint32_t off = (uint32_t)(kc * 16 * ASP + nf2 * 16) * 2;
                LDMX4T(vb_h[0], vb_h[1], vb_h[2], vb_h[3], vh_a + off);
                LDMX4T(vb_l[0], vb_l[1], vb_l[2], vb_l[3], vl_a + off);
                MMA16816(o[nf2*2], pah[0], pah[1], pah[2], pah[3], vb_h[0], vb_h[1]);
                MMA16816(o[nf2*2], pah[0], pah[1], pah[2], pah[3], vb_l[0], vb_l[1]);
                MMA16816(o[nf2*2], pal[0], pal[1], pal[2], pal[3], vb_h[0], vb_h[1]);
                MMA16816(o[nf2*2+1], pah[0], pah[1], pah[2], pah[3], vb_h[2], vb_h[3]);
                MMA16816(o[nf2*2+1], pah[0], pah[1], pah[2], pah[3], vb_l[2], vb_l[3]);
                MMA16816(o[nf2*2+1], pal[0], pal[1], pal[2], pal[3], vb_h[2], vb_h[3]);
            }
        }
    }

    lsum0 += __shfl_xor_sync(0xffffffffu, lsum0, 1);
    lsum0 += __shfl_xor_sync(0xffffffffu, lsum0, 2);
    lsum1 += __shfl_xor_sync(0xffffffffu, lsum1, 1);
    lsum1 += __shfl_xor_sync(0xffffffffu, lsum1, 2);
    const float inv0 = 1.0f / lsum0;
    const float inv1 = 1.0f / lsum1;

    __half* yp0 = g_yf + ((size_t)(b * T_) + row0) * C_ + h * D_ + (lane & 3) * 2;
    __half* yp1 = yp0 + (size_t)8 * C_;
    #pragma unroll
    for (int nf = 0; nf < 8; nf++) {
        *(__half2*)(yp0 + nf * 8) = __halves2half2(
            __float2half_rn(o[nf][0] * inv0), __float2half_rn(o[nf][1] * inv0));
        *(__half2*)(yp1 + nf * 8) = __halves2half2(
            __float2half_rn(o[nf][2] * inv1), __float2half_rn(o[nf][3] * inv1));
    }
}

// ---------------------------------------------------------------------------
extern "C" void kernel_launch(void* const* d_in, const int* in_sizes, int n_in,
                              void* d_out, int out_size)
{
    (void)in_sizes; (void)n_in; (void)out_size;
    const float* x    = (const float*)d_in[0];
    const int*   spl  = (const int*)  d_in[1];
    const float* Wqkv = (const float*)d_in[2];
    const float* bqkv = (const float*)d_in[3];
    const float* Wprj = (const float*)d_in[4];
    const float* bprj = (const float*)d_in[5];
    float* out = (float*)d_out;

    cudaFuncSetAttribute(gemm_f16_kernel<0>,
                         cudaFuncAttributeMaxDynamicSharedMemorySize, GSMEM);
    cudaFuncSetAttribute(gemm_f16_kernel<1>,
                         cudaFuncAttributeMaxDynamicSharedMemorySize, GSMEM);

    __half *xf, *wqf, *wpf, *yf;
    cudaGetSymbolAddress((void**)&xf,  g_xf);
    cudaGetSymbolAddress((void**)&wqf, g_wqf);
    cudaGetSymbolAddress((void**)&wpf, g_wpf);
    cudaGetSymbolAddress((void**)&yf,  g_yf);

    // 0) convert inputs to fp16
    cvt_f16<<<(B_*T_*C_/4 + 255)/256, 256>>>(x, xf, B_*T_*C_/4);
    cvt_f16<<<(3*C_*C_/4 + 255)/256, 256>>>(Wqkv, wqf, 3*C_*C_/4);
    cvt_f16<<<(C_*C_/4 + 255)/256, 256>>>(Wprj, wpf, C_*C_/4);

    // 1) QKV projection (fp16 HMMA) -> g_Qf/g_Kf fp16, g_Vh/g_Vl bf16
    gemm_f16_kernel<0><<<dim3(3*C_/128, B_*T_/128), 256, GSMEM>>>(
        xf, wqf, bqkv, nullptr);

    // 2) attention -> g_yf fp16
    attn_kernel<<<dim3(T_/128, H_, B_), 256>>>(spl);

    // 3) output projection (fp16 HMMA) -> d_out
    gemm_f16_kernel<1><<<dim3(C_/128, B_*T_/128), 256, GSMEM>>>(
        yf, wpf, bprj, out);
}

// round 11
// speedup vs baseline: 1.0923x; 1.0923x over previous
#include <cuda_runtime.h>
#include <cuda_bf16.h>
#include <cuda_fp16.h>
#include <math.h>
#include <stdint.h>

// Problem constants
#define B_ 2
#define T_ 2048
#define C_ 1024
#define H_ 16
#define D_ 64
#define WIN_ 512
#define K_ 1024

// GEMM tiling: fp16 single-product, BK=32 per stage (2x K16), 4-stage cp.async
#define SP 24                       // padded row stride per K16 tile (fp16) = 48 B
#define TILE_B (128 * SP * 2)       // 6144 B per 128x16 tile
#define STAGE_B (4 * TILE_B)        // A0,A1,B0,B1 = 24576 B
#define NSTAGE 4                    // power of 2 (ring mask)
#define GSMEM (NSTAGE * STAGE_B)    // 98304 B

// Attention smem: Qf[128], Kf[64], Vf[64] fp16, stride ASP
#define ASP 72

// ---------------- scratch (allocation-free) ----------------
__device__ __half g_Qf[B_*H_*T_*D_];
__device__ __half g_Kf[B_*H_*T_*D_];
__device__ __half g_Vf[B_*H_*T_*D_];
__device__ __half g_xf[B_*T_*C_];
__device__ __half g_wqf[3*C_*C_];
__device__ __half g_wpf[C_*C_];
__device__ __half g_yf[B_*T_*C_];

__device__ __forceinline__ uint32_t smem_u32(const void* p) {
    uint32_t a;
    asm("{ .reg .u64 t; cvta.to.shared.u64 t, %1; cvt.u32.u64 %0, t; }"
        : "=r"(a) : "l"(p));
    return a;
}
#define LDMX4(r0, r1, r2, r3, addr)                                          \
    asm volatile("ldmatrix.sync.aligned.m8n8.x4.shared.b16 {%0,%1,%2,%3}, [%4];" \
        : "=r"(r0), "=r"(r1), "=r"(r2), "=r"(r3) : "r"(addr))
#define LDMX4T(r0, r1, r2, r3, addr)                                         \
    asm volatile("ldmatrix.sync.aligned.m8n8.x4.trans.shared.b16 {%0,%1,%2,%3}, [%4];" \
        : "=r"(r0), "=r"(r1), "=r"(r2), "=r"(r3) : "r"(addr))
// fp16 HMMA
#define MMAH16816(c, a0, a1, a2, a3, b0, b1)                                 \
    asm volatile("mma.sync.aligned.m16n8k16.row.col.f32.f16.f16.f32 "        \
        "{%0,%1,%2,%3}, {%4,%5,%6,%7}, {%8,%9}, {%0,%1,%2,%3};"              \
        : "+f"((c)[0]), "+f"((c)[1]), "+f"((c)[2]), "+f"((c)[3])             \
        : "r"(a0), "r"(a1), "r"(a2), "r"(a3), "r"(b0), "r"(b1))
#define CP16(dst, src)                                                       \
    asm volatile("cp.async.cg.shared.global [%0], [%1], 16;" :: "r"(dst), "l"(src))
#define CP_COMMIT() asm volatile("cp.async.commit_group;" ::: "memory")
#define CP_WAIT(n)  asm volatile("cp.async.wait_group %0;" :: "n"(n) : "memory")

__device__ __forceinline__ uint32_t packh2(float a, float b) {
    __half2 h = __floats2half2_rn(a, b);
    return *(uint32_t*)&h;
}

// ---------------- convert fp32 -> fp16 ----------------
__global__ __launch_bounds__(256) void cvt_f16(
    const float* __restrict__ s, __half* __restrict__ d, int n4)
{
    int i = blockIdx.x * 256 + threadIdx.x;
    if (i >= n4) return;
    float4 v = ((const float4*)s)[i];
    ((__half2*)d)[2*i]   = __floats2half2_rn(v.x, v.y);
    ((__half2*)d)[2*i+1] = __floats2half2_rn(v.z, v.w);
}

// ---------------- fp16 single-product tensor-core GEMM --------------------
// D[m,n] = sum_k A[m,k]*W[n,k] + bias[n]
// CTA 128x128, BK=32/stage (2 K16 sub-slabs per barrier), 256 threads =
// 8 warps (4m x 2n), warp tile 32x64, 4-stage cp.async, direct epilogue.
// MODE 0: q,k,v -> fp16 scatter [B,H,T,d].  MODE 1: fp32 row-major out.
template <int MODE>
__global__ __launch_bounds__(256, 2) void gemm_f16_kernel(
    const __half* __restrict__ Af, const __half* __restrict__ Bf,
    const float* __restrict__ bias, float* __restrict__ Cout)
{
    extern __shared__ char smem[];
    const uint32_t sb = smem_u32(smem);
    const int tid = threadIdx.x;
    const int wid = tid >> 5;
    const int lane = tid & 31;
    const int warp_m = wid & 3;      // 4 x 32 rows
    const int warp_n = wid >> 2;     // 2 x 64 cols
    const int bn = blockIdx.x, bm = blockIdx.y;

    // cp.async: thread -> (A|B, row); 4x 16B per stage (2 sub-slabs x 2 chunks)
    const int ct = tid >> 7;          // 0=A, 1=B
    const int crow = tid & 127;
    const __half* const csrc = (ct == 0)
        ? Af + (size_t)(bm * 128 + crow) * K_
        : Bf + (size_t)(bn * 128 + crow) * K_;
    const uint32_t cd0 = sb + (uint32_t)(ct * 2 * TILE_B + crow * SP * 2);

    // ldmatrix per-lane byte offsets within a K16 tile
    const uint32_t aoff = (uint32_t)(
        (warp_m * 32 + (lane & 7) + ((lane >> 3) & 1) * 8) * SP
        + (lane >> 4) * 8) * 2;
    const uint32_t boff = (uint32_t)(
        (warp_n * 64 + (lane & 7) + (lane >> 4) * 8) * SP
        + ((lane >> 3) & 1) * 8) * 2;

    float acc[2][8][4];
    #pragma unroll
    for (int i = 0; i < 2; i++)
        #pragma unroll
        for (int j = 0; j < 8; j++)
            #pragma unroll
            for (int c = 0; c < 4; c++) acc[i][j][c] = 0.f;

    const int NT = K_ / 32;   // 32 stages

    #pragma unroll
    for (int st = 0; st < NSTAGE - 1; st++) {
        #pragma unroll
        for (int sub = 0; sub < 2; sub++) {
            const uint32_t db = cd0 + st * STAGE_B + sub * TILE_B;
            CP16(db,      csrc + st * 32 + sub * 16);
            CP16(db + 16, csrc + st * 32 + sub * 16 + 8);
        }
        CP_COMMIT();
    }

    for (int it = 0; it < NT; ++it) {
        CP_WAIT(NSTAGE - 2);
        __syncthreads();
        const uint32_t tb = sb + (uint32_t)(it & (NSTAGE - 1)) * STAGE_B;

        if (it + NSTAGE - 1 < NT) {
            const uint32_t db0 = cd0 + (uint32_t)((it + NSTAGE - 1) & (NSTAGE - 1)) * STAGE_B;
            #pragma unroll
            for (int sub = 0; sub < 2; sub++) {
                CP16(db0 + sub * TILE_B,      csrc + (it + NSTAGE - 1) * 32 + sub * 16);
                CP16(db0 + sub * TILE_B + 16, csrc + (it + NSTAGE - 1) * 32 + sub * 16 + 8);
            }
        }
        CP_COMMIT();

        #pragma unroll
        for (int sub = 0; sub < 2; sub++) {
            const uint32_t ta = tb + sub * TILE_B;            // A sub-slab
            const uint32_t tbb = tb + (2 + sub) * TILE_B;     // B sub-slab
            uint32_t af[2][4];
            #pragma unroll
            for (int mf = 0; mf < 2; mf++) {
                const uint32_t ao = ta + aoff + (uint32_t)(mf * 16 * SP) * 2;
                LDMX4(af[mf][0], af[mf][1], af[mf][2], af[mf][3], ao);
            }
            #pragma unroll
            for (int nf2 = 0; nf2 < 4; nf2++) {
                uint32_t bf[4];
                const uint32_t bo = tbb + boff + (uint32_t)(nf2 * 16 * SP) * 2;
                LDMX4(bf[0], bf[1], bf[2], bf[3], bo);
                #pragma unroll
                for (int mf = 0; mf < 2; mf++) {
                    MMAH16816(acc[mf][nf2*2],   af[mf][0], af[mf][1], af[mf][2], af[mf][3],
                              bf[0], bf[1]);
                    MMAH16816(acc[mf][nf2*2+1], af[mf][0], af[mf][1], af[mf][2], af[mf][3],
                              bf[2], bf[3]);
                }
            }
        }
    }
    CP_WAIT(0);

    // ---- direct-from-fragment epilogue ----
    const int g = lane >> 2, tg = lane & 3;
    #pragma unroll
    for (int mf = 0; mf < 2; mf++) {
        #pragma unroll
        for (int nf = 0; nf < 8; nf++) {
            const int gc = bn * 128 + warp_n * 64 + nf * 8 + tg * 2;
            const float b0 = bias[gc], b1 = bias[gc + 1];
            const int r0 = bm * 128 + warp_m * 32 + mf * 16 + g;
            const float v0 = acc[mf][nf][0] + b0, v1 = acc[mf][nf][1] + b1;
            const float v2 = acc[mf][nf][2] + b0, v3 = acc[mf][nf][3] + b1;
            if (MODE == 0) {
                const int sel = gc >> 10;
                const int within = gc & 1023;
                const int h = within >> 6;
                const int dd = within & 63;
                __half* dst = (sel == 0) ? g_Qf : ((sel == 1) ? g_Kf : g_Vf);
                #pragma unroll
                for (int rr = 0; rr < 2; rr++) {
                    const int m = r0 + rr * 8;
                    const int b = m >> 11, t = m & 2047;
                    const size_t o = (((size_t)(b * H_ + h)) * T_ + t) * D_ + dd;
                    *(__half2*)(dst + o) = __floats2half2_rn(rr ? v2 : v0,
                                                             rr ? v3 : v1);
                }
            } else {
                #pragma unroll
                for (int rr = 0; rr < 2; rr++) {
                    const int m = r0 + rr * 8;
                    float2 y;
                    y.x = rr ? v2 : v0;
                    y.y = rr ? v3 : v1;
                    *(float2*)(Cout + (size_t)m * C_ + gc) = y;
                }
            }
        }
    }
}

// ---------------------------------------------------------------------------
// Polynomial softcap+exp, ONE MUFU per element.
// p ~ exp(30*tanh(raw/240)) = exp2(raw*(d0 + d1*w + d2*w^2)), w = raw^2.
// Output range [2^-10.8, 2^10.8] -- fp16-normal friendly (enables fp16 PV).
// ---------------------------------------------------------------------------
__device__ __forceinline__ float softp(float raw, bool valid) {
    const float r = fminf(fmaxf(raw, -60.0f), 60.0f);
    const float w = r * r;
    const float u = r * fmaf(fmaf(7.2473e-12f, w, -1.0436162e-6f), w,
                             0.18033688011f);
    float p;
    asm("ex2.approx.f32 %0, %1;" : "=f"(p) : "f"(u));
    return valid ? p : 0.0f;
}

// ---------------------------------------------------------------------------
// Attention: 128 q-rows/CTA, 8 warps, 64-key tiles. ALL fp16 single-product:
// QK^T fp16, PV fp16 (p in [2^-10.8, 2^10.8] fits fp16 normals; products
// accumulate in fp32). Epilogue writes y as fp16 (proj GEMM input).
// ---------------------------------------------------------------------------
__global__ __launch_bounds__(256, 2) void attn_kernel(const int* __restrict__ spl)
{
    __shared__ __half Qf[128 * ASP];
    __shared__ __half Kf[64 * ASP];
    __shared__ __half Vf[64 * ASP];

    const int tid = threadIdx.x;
    const int wid = tid >> 5;      // 0..7
    const int lane = tid & 31;
    const int q0 = blockIdx.x * 128;
    const int h = blockIdx.y;
    const int b = blockIdx.z;
    const size_t bh = (size_t)(b * H_ + h) * T_;
    const int P = spl[b];

    // load Q: 128 rows x 8 uint4
    for (int i = tid; i < 1024; i += 256) {
        const int r = i >> 3;
        const int c8 = i & 7;
        *(uint4*)(Qf + r * ASP + c8 * 8) =
            *(const uint4*)(g_Qf + (bh + q0 + r) * D_ + c8 * 8);
    }

    const int a_row = wid * 16 + (lane & 7) + ((lane >> 3) & 1) * 8;
    const int a_kg = (lane >> 4) * 8;
    const uint32_t qf_a = smem_u32(Qf + a_row * ASP + a_kg);
    const int k_row = (lane & 7) + (lane >> 4) * 8;
    const int k_col = ((lane >> 3) & 1) * 8;
    const uint32_t kf_a = smem_u32(Kf + k_row * ASP + k_col);
    const int v_row = ((lane >> 3) & 1) * 8 + (lane & 7);
    const int v_col = (lane >> 4) * 8;
    const uint32_t vf_a = smem_u32(Vf + v_row * ASP + v_col);

    float o[8][4];
    #pragma unroll
    for (int i = 0; i < 8; i++)
        #pragma unroll
        for (int j = 0; j < 4; j++) o[i][j] = 0.f;
    float lsum0 = 0.f, lsum1 = 0.f;
    const int row0 = q0 + wid * 16 + (lane >> 2);

    for (int kt = 0; kt < T_ / 64; kt++) {
        const int k0 = kt * 64;
        const bool tv = (k0 < P) || ((k0 <= q0 + 127) && (k0 + 63 >= q0 - WIN_));
        if (!tv) continue;   // uniform across block

        __syncthreads();
        // K + V fp16: 2 arrays x 64 rows x 8 uint4 = 1024
        for (int i = tid; i < 1024; i += 256) {
            const int arr = i >> 9;
            const int r = (i >> 3) & 63;
            const int c8 = i & 7;
            const size_t src_o = (bh + k0 + r) * D_ + c8 * 8;
            if (arr == 0)
                *(uint4*)(Kf + r * ASP + c8 * 8) = *(const uint4*)(g_Kf + src_o);
            else
                *(uint4*)(Vf + r * ASP + c8 * 8) = *(const uint4*)(g_Vf + src_o);
        }
        __syncthreads();

        // ---- QK^T (single fp16 product) -> s[8][4] ----
        float s[8][4];
        #pragma unroll
        for (int i = 0; i < 8; i++)
            #pragma unroll
            for (int j = 0; j < 4; j++) s[i][j] = 0.f;

        #pragma unroll
        for (int kk4 = 0; kk4 < 4; kk4++) {
            uint32_t qa[4];
            LDMX4(qa[0], qa[1], qa[2], qa[3], qf_a + kk4 * 32);
            #pragma unroll
            for (int nf2 = 0; nf2 < 4; nf2++) {
                uint32_t kb[4];
                LDMX4(kb[0], kb[1], kb[2], kb[3],
                      kf_a + (uint32_t)(nf2 * 16 * ASP) * 2 + kk4 * 32);
                MMAH16816(s[nf2*2],   qa[0], qa[1], qa[2], qa[3], kb[0], kb[1]);
                MMAH16816(s[nf2*2+1], qa[0], qa[1], qa[2], qa[3], kb[2], kb[3]);
            }
        }

        // ---- softcap/mask/exp + C->A repack (fp16) + PV (fp16) ----
        #pragma unroll
        for (int kc = 0; kc < 4; kc++) {
            uint32_t pa[4];
            #pragma unroll
            for (int j = 0; j < 2; j++) {
                const int nf = kc * 2 + j;
                const int cb = k0 + nf * 8 + (lane & 3) * 2;
                const bool va0 = ((cb     <= row0)     && (row0     - cb     <= WIN_)) || (cb     < P);
                const bool va1 = ((cb + 1 <= row0)     && (row0     - cb - 1 <= WIN_)) || (cb + 1 < P);
                const bool va2 = ((cb     <= row0 + 8) && (row0 + 8 - cb     <= WIN_)) || (cb     < P);
                const bool va3 = ((cb + 1 <= row0 + 8) && (row0 + 8 - cb - 1 <= WIN_)) || (cb + 1 < P);
                const float p0 = softp(s[nf][0], va0);
                const float p1 = softp(s[nf][1], va1);
                const float p2 = softp(s[nf][2], va2);
                const float p3 = softp(s[nf][3], va3);
                lsum0 += p0 + p1;
                lsum1 += p2 + p3;
                pa[j*2]   = packh2(p0, p1);
                pa[j*2+1] = packh2(p2, p3);
            }
            #pragma unroll
            for (int nf2 = 0; nf2 < 4; nf2++) {
                uint32_t vb[4];
                const uint32_t off = (uint32_t)(kc * 16 * ASP + nf2 * 16) * 2;
                LDMX4T(vb[0], vb[1], vb[2], vb[3], vf_a + off);
                MMAH16816(o[nf2*2],   pa[0], pa[1], pa[2], pa[3], vb[0], vb[1]);
                MMAH16816(o[nf2*2+1], pa[0], pa[1], pa[2], pa[3], vb[2], vb[3]);
            }
        }
    }

    lsum0 += __shfl_xor_sync(0xffffffffu, lsum0, 1);
    lsum0 += __shfl_xor_sync(0xffffffffu, lsum0, 2);
    lsum1 += __shfl_xor_sync(0xffffffffu, lsum1, 1);
    lsum1 += __shfl_xor_sync(0xffffffffu, lsum1, 2);
    const float inv0 = 1.0f / lsum0;
    const float inv1 = 1.0f / lsum1;

    __half* yp0 = g_yf + ((size_t)(b * T_) + row0) * C_ + h * D_ + (lane & 3) * 2;
    __half* yp1 = yp0 + (size_t)8 * C_;
    #pragma unroll
    for (int nf = 0; nf < 8; nf++) {
        *(__half2*)(yp0 + nf * 8) = __floats2half2_rn(o[nf][0] * inv0,
                                                      o[nf][1] * inv0);
        *(__half2*)(yp1 + nf * 8) = __floats2half2_rn(o[nf][2] * inv1,
                                                      o[nf][3] * inv1);
    }
}

// ---------------------------------------------------------------------------
extern "C" void kernel_launch(void* const* d_in, const int* in_sizes, int n_in,
                              void* d_out, int out_size)
{
    (void)in_sizes; (void)n_in; (void)out_size;
    const float* x    = (const float*)d_in[0];
    const int*   spl  = (const int*)  d_in[1];
    const float* Wqkv = (const float*)d_in[2];
    const float* bqkv = (const float*)d_in[3];
    const float* Wprj = (const float*)d_in[4];
    const float* bprj = (const float*)d_in[5];
    float* out = (float*)d_out;

    cudaFuncSetAttribute(gemm_f16_kernel<0>,
                         cudaFuncAttributeMaxDynamicSharedMemorySize, GSMEM);
    cudaFuncSetAttribute(gemm_f16_kernel<1>,
                         cudaFuncAttributeMaxDynamicSharedMemorySize, GSMEM);

    __half *xf, *wqf, *wpf, *yf;
    cudaGetSymbolAddress((void**)&xf,  g_xf);
    cudaGetSymbolAddress((void**)&wqf, g_wqf);
    cudaGetSymbolAddress((void**)&wpf, g_wpf);
    cudaGetSymbolAddress((void**)&yf,  g_yf);

    // 0) convert inputs to fp16
    cvt_f16<<<(B_*T_*C_/4 + 255)/256, 256>>>(x, xf, B_*T_*C_/4);
    cvt_f16<<<(3*C_*C_/4 + 255)/256, 256>>>(Wqkv, wqf, 3*C_*C_/4);
    cvt_f16<<<(C_*C_/4 + 255)/256, 256>>>(Wprj, wpf, C_*C_/4);

    // 1) QKV projection (fp16 HMMA) -> g_Qf/g_Kf/g_Vf
    gemm_f16_kernel<0><<<dim3(3*C_/128, B_*T_/128), 256, GSMEM>>>(
        xf, wqf, bqkv, nullptr);

    // 2) attention (all-fp16 MMA) -> g_yf
    attn_kernel<<<dim3(T_/128, H_, B_), 256>>>(spl);

    // 3) output projection (fp16 HMMA) -> d_out
    gemm_f16_kernel<1><<<dim3(C_/128, B_*T_/128), 256, GSMEM>>>(
        yf, wpf, bprj, out);
}

// round 13
// speedup vs baseline: 1.1486x; 1.0515x over previous
#include <cuda_runtime.h>
#include <cuda_bf16.h>
#include <cuda_fp16.h>
#include <math.h>
#include <stdint.h>

// Problem constants
#define B_ 2
#define T_ 2048
#define C_ 1024
#define H_ 16
#define D_ 64
#define WIN_ 512
#define K_ 1024

// GEMM tiling: CTA 256(M)x128(N), fp16 single-product, BK=32/stage, 4 stages
#define SP 24                        // padded row stride per K16 tile (fp16) = 48 B
#define TILE_A_B (256 * SP * 2)      // 12288 B per 256x16 A tile
#define TILE_B_B (128 * SP * 2)      // 6144 B per 128x16 B tile
#define STAGE_B (2 * (TILE_A_B + TILE_B_B))   // 36864 B (2 K16 sub-slabs)
#define NSTAGE 4                     // power of 2 (ring mask)
#define GSMEM (NSTAGE * STAGE_B)     // 147456 B

// Attention smem: Qf[128], Kf[64], Vf[64] fp16, stride ASP
#define ASP 72

// ---------------- scratch (allocation-free) ----------------
__device__ __half g_Qf[B_*H_*T_*D_];
__device__ __half g_Kf[B_*H_*T_*D_];
__device__ __half g_Vf[B_*H_*T_*D_];
__device__ __half g_xf[B_*T_*C_];
__device__ __half g_wqf[3*C_*C_];
__device__ __half g_wpf[C_*C_];
__device__ __half g_yf[B_*T_*C_];

__device__ __forceinline__ uint32_t smem_u32(const void* p) {
    uint32_t a;
    asm("{ .reg .u64 t; cvta.to.shared.u64 t, %1; cvt.u32.u64 %0, t; }"
        : "=r"(a) : "l"(p));
    return a;
}
#define LDMX4(r0, r1, r2, r3, addr)                                          \
    asm volatile("ldmatrix.sync.aligned.m8n8.x4.shared.b16 {%0,%1,%2,%3}, [%4];" \
        : "=r"(r0), "=r"(r1), "=r"(r2), "=r"(r3) : "r"(addr))
#define LDMX4T(r0, r1, r2, r3, addr)                                         \
    asm volatile("ldmatrix.sync.aligned.m8n8.x4.trans.shared.b16 {%0,%1,%2,%3}, [%4];" \
        : "=r"(r0), "=r"(r1), "=r"(r2), "=r"(r3) : "r"(addr))
// fp16 HMMA
#define MMAH16816(c, a0, a1, a2, a3, b0, b1)                                 \
    asm volatile("mma.sync.aligned.m16n8k16.row.col.f32.f16.f16.f32 "        \
        "{%0,%1,%2,%3}, {%4,%5,%6,%7}, {%8,%9}, {%0,%1,%2,%3};"              \
        : "+f"((c)[0]), "+f"((c)[1]), "+f"((c)[2]), "+f"((c)[3])             \
        : "r"(a0), "r"(a1), "r"(a2), "r"(a3), "r"(b0), "r"(b1))
#define CP16(dst, src)                                                       \
    asm volatile("cp.async.cg.shared.global [%0], [%1], 16;" :: "r"(dst), "l"(src))
#define CP_COMMIT() asm volatile("cp.async.commit_group;" ::: "memory")
#define CP_WAIT(n)  asm volatile("cp.async.wait_group %0;" :: "n"(n) : "memory")

__device__ __forceinline__ uint32_t packh2(float a, float b) {
    __half2 h = __floats2half2_rn(a, b);
    return *(uint32_t*)&h;
}

// ---------------- convert fp32 -> fp16 ----------------
__global__ __launch_bounds__(256) void cvt_f16(
    const float* __restrict__ s, __half* __restrict__ d, int n4)
{
    int i = blockIdx.x * 256 + threadIdx.x;
    if (i >= n4) return;
    float4 v = ((const float4*)s)[i];
    ((__half2*)d)[2*i]   = __floats2half2_rn(v.x, v.y);
    ((__half2*)d)[2*i+1] = __floats2half2_rn(v.z, v.w);
}

// ---------------- fp16 tensor-core GEMM, CTA 256x128 ----------------------
// D[m,n] = sum_k A[m,k]*W[n,k] + bias[n]
// 512 threads = 16 warps (4m x 4n), warp tile 64x32 (coverage 256x128 ✓),
// BK=32/stage (2 K16 sub-slabs per barrier), 4-stage cp.async, direct epilogue.
// MODE 0: q,k,v -> fp16 scatter [B,H,T,d].  MODE 1: fp32 row-major out.
template <int MODE>
__global__ __launch_bounds__(512, 1) void gemm_f16_kernel(
    const __half* __restrict__ Af, const __half* __restrict__ Bf,
    const float* __restrict__ bias, float* __restrict__ Cout)
{
    extern __shared__ char smem[];
    const uint32_t sb = smem_u32(smem);
    const int tid = threadIdx.x;
    const int wid = tid >> 5;
    const int lane = tid & 31;
    const int warp_m = wid & 3;      // 4 x 64 rows = 256
    const int warp_n = wid >> 2;     // 4 x 32 cols = 128
    const int bn = blockIdx.x, bm = blockIdx.y;

    // cp.async mapping: tid<256 -> A row tid; tid in [256,384) -> B row tid-256.
    const bool is_a = tid < 256;
    const bool active = tid < 384;
    const int crow = is_a ? tid : (tid - 256);
    const __half* csrc = is_a
        ? Af + (size_t)(bm * 256 + crow) * K_
        : Bf + (size_t)(bn * 128 + (active ? crow : 0)) * K_;
    const uint32_t cbase = is_a
        ? sb + (uint32_t)(crow * SP * 2)
        : sb + (uint32_t)(2 * TILE_A_B + crow * SP * 2);
    const uint32_t csub = is_a ? TILE_A_B : TILE_B_B;

    // ldmatrix per-lane byte offsets within a K16 tile
    const uint32_t aoff = (uint32_t)(
        (warp_m * 64 + (lane & 7) + ((lane >> 3) & 1) * 8) * SP
        + (lane >> 4) * 8) * 2;
    const uint32_t boff = (uint32_t)(2 * TILE_A_B) + (uint32_t)(
        (warp_n * 32 + (lane & 7) + (lane >> 4) * 8) * SP
        + ((lane >> 3) & 1) * 8) * 2;

    float acc[4][4][4];
    #pragma unroll
    for (int i = 0; i < 4; i++)
        #pragma unroll
        for (int j = 0; j < 4; j++)
            #pragma unroll
            for (int c = 0; c < 4; c++) acc[i][j][c] = 0.f;

    const int NT = K_ / 32;   // 32 stages

    #pragma unroll
    for (int st = 0; st < NSTAGE - 1; st++) {
        if (active) {
            #pragma unroll
            for (int sub = 0; sub < 2; sub++) {
                const uint32_t db = cbase + st * STAGE_B + sub * csub;
                CP16(db,      csrc + st * 32 + sub * 16);
                CP16(db + 16, csrc + st * 32 + sub * 16 + 8);
            }
        }
        CP_COMMIT();
    }

    for (int it = 0; it < NT; ++it) {
        CP_WAIT(NSTAGE - 2);
        __syncthreads();
        const uint32_t tb = sb + (uint32_t)(it & (NSTAGE - 1)) * STAGE_B;

        if (active && (it + NSTAGE - 1 < NT)) {
            const uint32_t db0 = cbase + (uint32_t)((it + NSTAGE - 1) & (NSTAGE - 1)) * STAGE_B;
            #pragma unroll
            for (int sub = 0; sub < 2; sub++) {
                CP16(db0 + sub * csub,      csrc + (it + NSTAGE - 1) * 32 + sub * 16);
                CP16(db0 + sub * csub + 16, csrc + (it + NSTAGE - 1) * 32 + sub * 16 + 8);
            }
        }
        CP_COMMIT();

        #pragma unroll
        for (int sub = 0; sub < 2; sub++) {
            const uint32_t ta  = tb + sub * TILE_A_B;      // A sub-slab
            const uint32_t tbb = tb + sub * TILE_B_B;      // B sub-slab (boff has 2*TILE_A_B)
            uint32_t af[4][4];
            #pragma unroll
            for (int mf = 0; mf < 4; mf++) {
                const uint32_t ao = ta + aoff + (uint32_t)(mf * 16 * SP) * 2;
                LDMX4(af[mf][0], af[mf][1], af[mf][2], af[mf][3], ao);
            }
            #pragma unroll
            for (int nf2 = 0; nf2 < 2; nf2++) {
                uint32_t bf[4];
                const uint32_t bo = tbb + boff + (uint32_t)(nf2 * 16 * SP) * 2;
                LDMX4(bf[0], bf[1], bf[2], bf[3], bo);
                #pragma unroll
                for (int mf = 0; mf < 4; mf++) {
                    MMAH16816(acc[mf][nf2*2],   af[mf][0], af[mf][1], af[mf][2], af[mf][3],
                              bf[0], bf[1]);
                    MMAH16816(acc[mf][nf2*2+1], af[mf][0], af[mf][1], af[mf][2], af[mf][3],
                              bf[2], bf[3]);
                }
            }
        }
    }
    CP_WAIT(0);

    // ---- direct-from-fragment epilogue ----
    const int g = lane >> 2, tg = lane & 3;
    #pragma unroll
    for (int mf = 0; mf < 4; mf++) {
        #pragma unroll
        for (int nf = 0; nf < 4; nf++) {
            const int gc = bn * 128 + warp_n * 32 + nf * 8 + tg * 2;
            const float b0 = bias[gc], b1 = bias[gc + 1];
            const int r0 = bm * 256 + warp_m * 64 + mf * 16 + g;
            const float v0 = acc[mf][nf][0] + b0, v1 = acc[mf][nf][1] + b1;
            const float v2 = acc[mf][nf][2] + b0, v3 = acc[mf][nf][3] + b1;
            if (MODE == 0) {
                const int sel = gc >> 10;
                const int within = gc & 1023;
                const int h = within >> 6;
                const int dd = within & 63;
                __half* dst = (sel == 0) ? g_Qf : ((sel == 1) ? g_Kf : g_Vf);
                #pragma unroll
                for (int rr = 0; rr < 2; rr++) {
                    const int m = r0 + rr * 8;
                    const int b = m >> 11, t = m & 2047;
                    const size_t o = (((size_t)(b * H_ + h)) * T_ + t) * D_ + dd;
                    *(__half2*)(dst + o) = __floats2half2_rn(rr ? v2 : v0,
                                                             rr ? v3 : v1);
                }
            } else {
                #pragma unroll
                for (int rr = 0; rr < 2; rr++) {
                    const int m = r0 + rr * 8;
                    float2 y;
                    y.x = rr ? v2 : v0;
                    y.y = rr ? v3 : v1;
                    *(float2*)(Cout + (size_t)m * C_ + gc) = y;
                }
            }
        }
    }
}

// ---------------------------------------------------------------------------
// Polynomial softcap+exp, ONE MUFU per element.
// p ~ exp(30*tanh(raw/240)) = exp2(raw*(d0 + d1*w + d2*w^2)), w = raw^2.
// Output range [2^-10.8, 2^10.8] -- fp16-normal friendly (enables fp16 PV).
// ---------------------------------------------------------------------------
__device__ __forceinline__ float softp(float raw, bool valid) {
    const float r = fminf(fmaxf(raw, -60.0f), 60.0f);
    const float w = r * r;
    const float u = r * fmaf(fmaf(7.2473e-12f, w, -1.0436162e-6f), w,
                             0.18033688011f);
    float p;
    asm("ex2.approx.f32 %0, %1;" : "=f"(p) : "f"(u));
    return valid ? p : 0.0f;
}

// ---------------------------------------------------------------------------
// Attention: 128 q-rows/CTA, 8 warps, 64-key tiles. ALL fp16 single-product.
// ---------------------------------------------------------------------------
__global__ __launch_bounds__(256, 2) void attn_kernel(const int* __restrict__ spl)
{
    __shared__ __half Qf[128 * ASP];
    __shared__ __half Kf[64 * ASP];
    __shared__ __half Vf[64 * ASP];

    const int tid = threadIdx.x;
    const int wid = tid >> 5;      // 0..7
    const int lane = tid & 31;
    const int q0 = blockIdx.x * 128;
    const int h = blockIdx.y;
    const int b = blockIdx.z;
    const size_t bh = (size_t)(b * H_ + h) * T_;
    const int P = spl[b];

    // load Q: 128 rows x 8 uint4
    for (int i = tid; i < 1024; i += 256) {
        const int r = i >> 3;
        const int c8 = i & 7;
        *(uint4*)(Qf + r * ASP + c8 * 8) =
            *(const uint4*)(g_Qf + (bh + q0 + r) * D_ + c8 * 8);
    }

    const int a_row = wid * 16 + (lane & 7) + ((lane >> 3) & 1) * 8;
    const int a_kg = (lane >> 4) * 8;
    const uint32_t qf_a = smem_u32(Qf + a_row * ASP + a_kg);
    const int k_row = (lane & 7) + (lane >> 4) * 8;
    const int k_col = ((lane >> 3) & 1) * 8;
    const uint32_t kf_a = smem_u32(Kf + k_row * ASP + k_col);
    const int v_row = ((lane >> 3) & 1) * 8 + (lane & 7);
    const int v_col = (lane >> 4) * 8;
    const uint32_t vf_a = smem_u32(Vf + v_row * ASP + v_col);

    float o[8][4];
    #pragma unroll
    for (int i = 0; i < 8; i++)
        #pragma unroll
        for (int j = 0; j < 4; j++) o[i][j] = 0.f;
    float lsum0 = 0.f, lsum1 = 0.f;
    const int row0 = q0 + wid * 16 + (lane >> 2);

    for (int kt = 0; kt < T_ / 64; kt++) {
        const int k0 = kt * 64;
        const bool tv = (k0 < P) || ((k0 <= q0 + 127) && (k0 + 63 >= q0 - WIN_));
        if (!tv) continue;   // uniform across block

        __syncthreads();
        for (int i = tid; i < 1024; i += 256) {
            const int arr = i >> 9;
            const int r = (i >> 3) & 63;
            const int c8 = i & 7;
            const size_t src_o = (bh + k0 + r) * D_ + c8 * 8;
            if (arr == 0)
                *(uint4*)(Kf + r * ASP + c8 * 8) = *(const uint4*)(g_Kf + src_o);
            else
                *(uint4*)(Vf + r * ASP + c8 * 8) = *(const uint4*)(g_Vf + src_o);
        }
        __syncthreads();

        // ---- QK^T (single fp16 product) -> s[8][4] ----
        float s[8][4];
        #pragma unroll
        for (int i = 0; i < 8; i++)
            #pragma unroll
            for (int j = 0; j < 4; j++) s[i][j] = 0.f;

        #pragma unroll
        for (int kk4 = 0; kk4 < 4; kk4++) {
            uint32_t qa[4];
            LDMX4(qa[0], qa[1], qa[2], qa[3], qf_a + kk4 * 32);
            #pragma unroll
            for (int nf2 = 0; nf2 < 4; nf2++) {
                uint32_t kb[4];
                LDMX4(kb[0], kb[1], kb[2], kb[3],
                      kf_a + (uint32_t)(nf2 * 16 * ASP) * 2 + kk4 * 32);
                MMAH16816(s[nf2*2],   qa[0], qa[1], qa[2], qa[3], kb[0], kb[1]);
                MMAH16816(s[nf2*2+1], qa[0], qa[1], qa[2], qa[3], kb[2], kb[3]);
            }
        }

        // ---- softcap/mask/exp + C->A repack (fp16) + PV (fp16) ----
        #pragma unroll
        for (int kc = 0; kc < 4; kc++) {
            uint32_t pa[4];
            #pragma unroll
            for (int j = 0; j < 2; j++) {
                const int nf = kc * 2 + j;
                const int cb = k0 + nf * 8 + (lane & 3) * 2;
                const bool va0 = ((cb     <= row0)     && (row0     - cb     <= WIN_)) || (cb     < P);
                const bool va1 = ((cb + 1 <= row0)     && (row0     - cb - 1 <= WIN_)) || (cb + 1 < P);
                const bool va2 = ((cb     <= row0 + 8) && (row0 + 8 - cb     <= WIN_)) || (cb     < P);
                const bool va3 = ((cb + 1 <= row0 + 8) && (row0 + 8 - cb - 1 <= WIN_)) || (cb + 1 < P);
                const float p0 = softp(s[nf][0], va0);
                const float p1 = softp(s[nf][1], va1);
                const float p2 = softp(s[nf][2], va2);
                const float p3 = softp(s[nf][3], va3);
                lsum0 += p0 + p1;
                lsum1 += p2 + p3;
                pa[j*2]   = packh2(p0, p1);
                pa[j*2+1] = packh2(p2, p3);
            }
            #pragma unroll
            for (int nf2 = 0; nf2 < 4; nf2++) {
                uint32_t vb[4];
                const uint32_t off = (uint32_t)(kc * 16 * ASP + nf2 * 16) * 2;
                LDMX4T(vb[0], vb[1], vb[2], vb[3], vf_a + off);
                MMAH16816(o[nf2*2],   pa[0], pa[1], pa[2], pa[3], vb[0], vb[1]);
                MMAH16816(o[nf2*2+1], pa[0], pa[1], pa[2], pa[3], vb[2], vb[3]);
            }
        }
    }

    lsum0 += __shfl_xor_sync(0xffffffffu, lsum0, 1);
    lsum0 += __shfl_xor_sync(0xffffffffu, lsum0, 2);
    lsum1 += __shfl_xor_sync(0xffffffffu, lsum1, 1);
    lsum1 += __shfl_xor_sync(0xffffffffu, lsum1, 2);
    const float inv0 = 1.0f / lsum0;
    const float inv1 = 1.0f / lsum1;

    __half* yp0 = g_yf + ((size_t)(b * T_) + row0) * C_ + h * D_ + (lane & 3) * 2;
    __half* yp1 = yp0 + (size_t)8 * C_;
    #pragma unroll
    for (int nf = 0; nf < 8; nf++) {
        *(__half2*)(yp0 + nf * 8) = __floats2half2_rn(o[nf][0] * inv0,
                                                      o[nf][1] * inv0);
        *(__half2*)(yp1 + nf * 8) = __floats2half2_rn(o[nf][2] * inv1,
                                                      o[nf][3] * inv1);
    }
}

// ---------------------------------------------------------------------------
extern "C" void kernel_launch(void* const* d_in, const int* in_sizes, int n_in,
                              void* d_out, int out_size)
{
    (void)in_sizes; (void)n_in; (void)out_size;
    const float* x    = (const float*)d_in[0];
    const int*   spl  = (const int*)  d_in[1];
    const float* Wqkv = (const float*)d_in[2];
    const float* bqkv = (const float*)d_in[3];
    const float* Wprj = (const float*)d_in[4];
    const float* bprj = (const float*)d_in[5];
    float* out = (float*)d_out;

    cudaFuncSetAttribute(gemm_f16_kernel<0>,
                         cudaFuncAttributeMaxDynamicSharedMemorySize, GSMEM);
    cudaFuncSetAttribute(gemm_f16_kernel<1>,
                         cudaFuncAttributeMaxDynamicSharedMemorySize, GSMEM);

    __half *xf, *wqf, *wpf, *yf;
    cudaGetSymbolAddress((void**)&xf,  g_xf);
    cudaGetSymbolAddress((void**)&wqf, g_wqf);
    cudaGetSymbolAddress((void**)&wpf, g_wpf);
    cudaGetSymbolAddress((void**)&yf,  g_yf);

    // 0) convert inputs to fp16
    cvt_f16<<<(B_*T_*C_/4 + 255)/256, 256>>>(x, xf, B_*T_*C_/4);
    cvt_f16<<<(3*C_*C_/4 + 255)/256, 256>>>(Wqkv, wqf, 3*C_*C_/4);
    cvt_f16<<<(C_*C_/4 + 255)/256, 256>>>(Wprj, wpf, C_*C_/4);

    // 1) QKV projection (fp16 HMMA, 256x128 tiles) -> g_Qf/g_Kf/g_Vf
    gemm_f16_kernel<0><<<dim3(3*C_/128, B_*T_/256), 512, GSMEM>>>(
        xf, wqf, bqkv, nullptr);

    // 2) attention (all-fp16 MMA) -> g_yf
    attn_kernel<<<dim3(T_/128, H_, B_), 256>>>(spl);

    // 3) output projection (fp16 HMMA, 256x128 tiles) -> d_out
    gemm_f16_kernel<1><<<dim3(C_/128, B_*T_/256), 512, GSMEM>>>(
        yf, wpf, bprj, out);
}

// round 14
// speedup vs baseline: 1.1885x; 1.0348x over previous
#include <cuda_runtime.h>
#include <cuda_bf16.h>
#include <cuda_fp16.h>
#include <math.h>
#include <stdint.h>

// Problem constants
#define B_ 2
#define T_ 2048
#define C_ 1024
#define H_ 16
#define D_ 64
#define WIN_ 512
#define K_ 1024

// GEMM tiling: CTA 256(M)x128(N), fp16, BK=64/stage (4x K16), 3-stage ring
#define SP 24                        // padded row stride per K16 tile (fp16) = 48 B
#define TILE_A_B (256 * SP * 2)      // 12288 B per 256x16 A tile
#define TILE_B_B (128 * SP * 2)      // 6144 B per 128x16 B tile
#define STAGE_B (4 * (TILE_A_B + TILE_B_B))   // 73728 B (4 K16 sub-slabs)
#define NSTAGE 3
#define GSMEM (NSTAGE * STAGE_B)     // 221184 B (216 KB), 1 CTA/SM

// Attention smem: Qf[128], Kf[64], Vf[64] fp16, stride ASP
#define ASP 72

// ---------------- scratch (allocation-free) ----------------
__device__ __half g_Qf[B_*H_*T_*D_];
__device__ __half g_Kf[B_*H_*T_*D_];
__device__ __half g_Vf[B_*H_*T_*D_];
__device__ __half g_xf[B_*T_*C_];
__device__ __half g_wqf[3*C_*C_];
__device__ __half g_wpf[C_*C_];
__device__ __half g_yf[B_*T_*C_];

__device__ __forceinline__ uint32_t smem_u32(const void* p) {
    uint32_t a;
    asm("{ .reg .u64 t; cvta.to.shared.u64 t, %1; cvt.u32.u64 %0, t; }"
        : "=r"(a) : "l"(p));
    return a;
}
#define LDMX4(r0, r1, r2, r3, addr)                                          \
    asm volatile("ldmatrix.sync.aligned.m8n8.x4.shared.b16 {%0,%1,%2,%3}, [%4];" \
        : "=r"(r0), "=r"(r1), "=r"(r2), "=r"(r3) : "r"(addr))
#define LDMX4T(r0, r1, r2, r3, addr)                                         \
    asm volatile("ldmatrix.sync.aligned.m8n8.x4.trans.shared.b16 {%0,%1,%2,%3}, [%4];" \
        : "=r"(r0), "=r"(r1), "=r"(r2), "=r"(r3) : "r"(addr))
// fp16 HMMA
#define MMAH16816(c, a0, a1, a2, a3, b0, b1)                                 \
    asm volatile("mma.sync.aligned.m16n8k16.row.col.f32.f16.f16.f32 "        \
        "{%0,%1,%2,%3}, {%4,%5,%6,%7}, {%8,%9}, {%0,%1,%2,%3};"              \
        : "+f"((c)[0]), "+f"((c)[1]), "+f"((c)[2]), "+f"((c)[3])             \
        : "r"(a0), "r"(a1), "r"(a2), "r"(a3), "r"(b0), "r"(b1))
#define CP16(dst, src)                                                       \
    asm volatile("cp.async.cg.shared.global [%0], [%1], 16;" :: "r"(dst), "l"(src))
#define CP_COMMIT() asm volatile("cp.async.commit_group;" ::: "memory")
#define CP_WAIT(n)  asm volatile("cp.async.wait_group %0;" :: "n"(n) : "memory")

__device__ __forceinline__ uint32_t packh2(float a, float b) {
    __half2 h = __floats2half2_rn(a, b);
    return *(uint32_t*)&h;
}

// ---------------- convert fp32 -> fp16 ----------------
__global__ __launch_bounds__(256) void cvt_f16(
    const float* __restrict__ s, __half* __restrict__ d, int n4)
{
    int i = blockIdx.x * 256 + threadIdx.x;
    if (i >= n4) return;
    float4 v = ((const float4*)s)[i];
    ((__half2*)d)[2*i]   = __floats2half2_rn(v.x, v.y);
    ((__half2*)d)[2*i+1] = __floats2half2_rn(v.z, v.w);
}

// ---------------- fp16 tensor-core GEMM, CTA 256x128, BK=64 ---------------
// D[m,n] = sum_k A[m,k]*W[n,k] + bias[n]
// 512 threads = 16 warps (4m x 4n), warp tile 64x32.
// 64 MMA/warp per barrier (4 K16 sub-slabs), 16 iterations, 3-stage ring.
// cp.async: 3072 16B chunks/stage spread as 6 per thread (all threads busy).
// MODE 0: q,k,v -> fp16 scatter [B,H,T,d].  MODE 1: fp32 row-major out.
template <int MODE>
__global__ __launch_bounds__(512, 1) void gemm_f16_kernel(
    const __half* __restrict__ Af, const __half* __restrict__ Bf,
    const float* __restrict__ bias, float* __restrict__ Cout)
{
    extern __shared__ char smem[];
    const uint32_t sb = smem_u32(smem);
    const int tid = threadIdx.x;
    const int wid = tid >> 5;
    const int lane = tid & 31;
    const int warp_m = wid & 3;      // 4 x 64 rows = 256
    const int warp_n = wid >> 2;     // 4 x 32 cols = 128
    const int bn = blockIdx.x, bm = blockIdx.y;

    // cp.async chunk map: chunk c = tid + i*512, i=0..5.
    // c < 2048: A chunk (row=c>>3, j=c&7); else B chunk (c-2048 likewise).
    // j selects k-halves: sub-slab = j>>1, within-slab 16B half = j&1.
    uint32_t cdst[6];
    const __half* csrc6[6];
    #pragma unroll
    for (int i = 0; i < 6; i++) {
        const int c = tid + i * 512;
        const bool isA = c < 2048;
        const int cc = isA ? c : c - 2048;
        const int row = cc >> 3, j = cc & 7;
        const int sub = j >> 1;
        cdst[i] = (isA ? (uint32_t)(sub * TILE_A_B)
                       : (uint32_t)(4 * TILE_A_B + sub * TILE_B_B))
                  + (uint32_t)(row * SP * 2 + (j & 1) * 16);
        csrc6[i] = (isA ? Af + (size_t)(bm * 256 + row) * K_
                        : Bf + (size_t)(bn * 128 + row) * K_) + j * 8;
    }

    // ldmatrix per-lane byte offsets within a K16 tile
    const uint32_t aoff = (uint32_t)(
        (warp_m * 64 + (lane & 7) + ((lane >> 3) & 1) * 8) * SP
        + (lane >> 4) * 8) * 2;
    const uint32_t boff = (uint32_t)(
        (warp_n * 32 + (lane & 7) + (lane >> 4) * 8) * SP
        + ((lane >> 3) & 1) * 8) * 2;

    float acc[4][4][4];
    #pragma unroll
    for (int i = 0; i < 4; i++)
        #pragma unroll
        for (int j = 0; j < 4; j++)
            #pragma unroll
            for (int c = 0; c < 4; c++) acc[i][j][c] = 0.f;

    const int NT = K_ / 64;   // 16 iterations

    // prologue: stages 0, 1
    #pragma unroll
    for (int st = 0; st < NSTAGE - 1; st++) {
        #pragma unroll
        for (int i = 0; i < 6; i++)
            CP16(sb + st * STAGE_B + cdst[i], csrc6[i] + st * 64);
        CP_COMMIT();
    }

    int cs = 0, pf = 2;
    for (int it = 0; it < NT; ++it) {
        CP_WAIT(1);                 // stage `it` resident
        __syncthreads();
        const uint32_t tb = sb + (uint32_t)cs * STAGE_B;

        if (it + 2 < NT) {
            const uint32_t db = sb + (uint32_t)pf * STAGE_B;
            #pragma unroll
            for (int i = 0; i < 6; i++)
                CP16(db + cdst[i], csrc6[i] + (it + 2) * 64);
        }
        CP_COMMIT();

        #pragma unroll
        for (int sub = 0; sub < 4; sub++) {
            const uint32_t ta  = tb + sub * TILE_A_B;
            const uint32_t tbb = tb + 4 * TILE_A_B + sub * TILE_B_B;
            uint32_t af[4][4];
            #pragma unroll
            for (int mf = 0; mf < 4; mf++) {
                const uint32_t ao = ta + aoff + (uint32_t)(mf * 16 * SP) * 2;
                LDMX4(af[mf][0], af[mf][1], af[mf][2], af[mf][3], ao);
            }
            #pragma unroll
            for (int nf2 = 0; nf2 < 2; nf2++) {
                uint32_t bf[4];
                const uint32_t bo = tbb + boff + (uint32_t)(nf2 * 16 * SP) * 2;
                LDMX4(bf[0], bf[1], bf[2], bf[3], bo);
                #pragma unroll
                for (int mf = 0; mf < 4; mf++) {
                    MMAH16816(acc[mf][nf2*2],   af[mf][0], af[mf][1], af[mf][2], af[mf][3],
                              bf[0], bf[1]);
                    MMAH16816(acc[mf][nf2*2+1], af[mf][0], af[mf][1], af[mf][2], af[mf][3],
                              bf[2], bf[3]);
                }
            }
        }
        cs = (cs == 2) ? 0 : cs + 1;
        pf = (pf == 2) ? 0 : pf + 1;
    }
    CP_WAIT(0);

    // ---- direct-from-fragment epilogue ----
    const int g = lane >> 2, tg = lane & 3;
    #pragma unroll
    for (int mf = 0; mf < 4; mf++) {
        #pragma unroll
        for (int nf = 0; nf < 4; nf++) {
            const int gc = bn * 128 + warp_n * 32 + nf * 8 + tg * 2;
            const float b0 = bias[gc], b1 = bias[gc + 1];
            const int r0 = bm * 256 + warp_m * 64 + mf * 16 + g;
            const float v0 = acc[mf][nf][0] + b0, v1 = acc[mf][nf][1] + b1;
            const float v2 = acc[mf][nf][2] + b0, v3 = acc[mf][nf][3] + b1;
            if (MODE == 0) {
                const int sel = gc >> 10;
                const int within = gc & 1023;
                const int h = within >> 6;
                const int dd = within & 63;
                __half* dst = (sel == 0) ? g_Qf : ((sel == 1) ? g_Kf : g_Vf);
                #pragma unroll
                for (int rr = 0; rr < 2; rr++) {
                    const int m = r0 + rr * 8;
                    const int b = m >> 11, t = m & 2047;
                    const size_t o = (((size_t)(b * H_ + h)) * T_ + t) * D_ + dd;
                    *(__half2*)(dst + o) = __floats2half2_rn(rr ? v2 : v0,
                                                             rr ? v3 : v1);
                }
            } else {
                #pragma unroll
                for (int rr = 0; rr < 2; rr++) {
                    const int m = r0 + rr * 8;
                    float2 y;
                    y.x = rr ? v2 : v0;
                    y.y = rr ? v3 : v1;
                    *(float2*)(Cout + (size_t)m * C_ + gc) = y;
                }
            }
        }
    }
}

// ---------------------------------------------------------------------------
// Polynomial softcap+exp, ONE MUFU per element.
// p ~ exp(30*tanh(raw/240)) = exp2(raw*(d0 + d1*w + d2*w^2)), w = raw^2.
// Output range [2^-10.8, 2^10.8] -- fp16-normal friendly (enables fp16 PV).
// ---------------------------------------------------------------------------
__device__ __forceinline__ float softp(float raw, bool valid) {
    const float r = fminf(fmaxf(raw, -60.0f), 60.0f);
    const float w = r * r;
    const float u = r * fmaf(fmaf(7.2473e-12f, w, -1.0436162e-6f), w,
                             0.18033688011f);
    float p;
    asm("ex2.approx.f32 %0, %1;" : "=f"(p) : "f"(u));
    return valid ? p : 0.0f;
}

// ---------------------------------------------------------------------------
// Attention: 128 q-rows/CTA, 8 warps, 64-key tiles. ALL fp16 single-product.
// ---------------------------------------------------------------------------
__global__ __launch_bounds__(256, 2) void attn_kernel(const int* __restrict__ spl)
{
    __shared__ __half Qf[128 * ASP];
    __shared__ __half Kf[64 * ASP];
    __shared__ __half Vf[64 * ASP];

    const int tid = threadIdx.x;
    const int wid = tid >> 5;      // 0..7
    const int lane = tid & 31;
    const int q0 = blockIdx.x * 128;
    const int h = blockIdx.y;
    const int b = blockIdx.z;
    const size_t bh = (size_t)(b * H_ + h) * T_;
    const int P = spl[b];

    // load Q: 128 rows x 8 uint4
    for (int i = tid; i < 1024; i += 256) {
        const int r = i >> 3;
        const int c8 = i & 7;
        *(uint4*)(Qf + r * ASP + c8 * 8) =
            *(const uint4*)(g_Qf + (bh + q0 + r) * D_ + c8 * 8);
    }

    const int a_row = wid * 16 + (lane & 7) + ((lane >> 3) & 1) * 8;
    const int a_kg = (lane >> 4) * 8;
    const uint32_t qf_a = smem_u32(Qf + a_row * ASP + a_kg);
    const int k_row = (lane & 7) + (lane >> 4) * 8;
    const int k_col = ((lane >> 3) & 1) * 8;
    const uint32_t kf_a = smem_u32(Kf + k_row * ASP + k_col);
    const int v_row = ((lane >> 3) & 1) * 8 + (lane & 7);
    const int v_col = (lane >> 4) * 8;
    const uint32_t vf_a = smem_u32(Vf + v_row * ASP + v_col);

    float o[8][4];
    #pragma unroll
    for (int i = 0; i < 8; i++)
        #pragma unroll
        for (int j = 0; j < 4; j++) o[i][j] = 0.f;
    float lsum0 = 0.f, lsum1 = 0.f;
    const int row0 = q0 + wid * 16 + (lane >> 2);

    for (int kt = 0; kt < T_ / 64; kt++) {
        const int k0 = kt * 64;
        const bool tv = (k0 < P) || ((k0 <= q0 + 127) && (k0 + 63 >= q0 - WIN_));
        if (!tv) continue;   // uniform across block

        __syncthreads();
        for (int i = tid; i < 1024; i += 256) {
            const int arr = i >> 9;
            const int r = (i >> 3) & 63;
            const int c8 = i & 7;
            const size_t src_o = (bh + k0 + r) * D_ + c8 * 8;
            if (arr == 0)
                *(uint4*)(Kf + r * ASP + c8 * 8) = *(const uint4*)(g_Kf + src_o);
            else
                *(uint4*)(Vf + r * ASP + c8 * 8) = *(const uint4*)(g_Vf + src_o);
        }
        __syncthreads();

        // ---- QK^T (single fp16 product) -> s[8][4] ----
        float s[8][4];
        #pragma unroll
        for (int i = 0; i < 8; i++)
            #pragma unroll
            for (int j = 0; j < 4; j++) s[i][j] = 0.f;

        #pragma unroll
        for (int kk4 = 0; kk4 < 4; kk4++) {
            uint32_t qa[4];
            LDMX4(qa[0], qa[1], qa[2], qa[3], qf_a + kk4 * 32);
            #pragma unroll
            for (int nf2 = 0; nf2 < 4; nf2++) {
                uint32_t kb[4];
                LDMX4(kb[0], kb[1], kb[2], kb[3],
                      kf_a + (uint32_t)(nf2 * 16 * ASP) * 2 + kk4 * 32);
                MMAH16816(s[nf2*2],   qa[0], qa[1], qa[2], qa[3], kb[0], kb[1]);
                MMAH16816(s[nf2*2+1], qa[0], qa[1], qa[2], qa[3], kb[2], kb[3]);
            }
        }

        // ---- softcap/mask/exp + C->A repack (fp16) + PV (fp16) ----
        #pragma unroll
        for (int kc = 0; kc < 4; kc++) {
            uint32_t pa[4];
            #pragma unroll
            for (int j = 0; j < 2; j++) {
                const int nf = kc * 2 + j;
                const int cb = k0 + nf * 8 + (lane & 3) * 2;
                const bool va0 = ((cb     <= row0)     && (row0     - cb     <= WIN_)) || (cb     < P);
                const bool va1 = ((cb + 1 <= row0)     && (row0     - cb - 1 <= WIN_)) || (cb + 1 < P);
                const bool va2 = ((cb     <= row0 + 8) && (row0 + 8 - cb     <= WIN_)) || (cb     < P);
                const bool va3 = ((cb + 1 <= row0 + 8) && (row0 + 8 - cb - 1 <= WIN_)) || (cb + 1 < P);
                const float p0 = softp(s[nf][0], va0);
                const float p1 = softp(s[nf][1], va1);
                const float p2 = softp(s[nf][2], va2);
                const float p3 = softp(s[nf][3], va3);
                lsum0 += p0 + p1;
                lsum1 += p2 + p3;
                pa[j*2]   = packh2(p0, p1);
                pa[j*2+1] = packh2(p2, p3);
            }
            #pragma unroll
            for (int nf2 = 0; nf2 < 4; nf2++) {
                uint32_t vb[4];
                const uint32_t off = (uint32_t)(kc * 16 * ASP + nf2 * 16) * 2;
                LDMX4T(vb[0], vb[1], vb[2], vb[3], vf_a + off);
                MMAH16816(o[nf2*2],   pa[0], pa[1], pa[2], pa[3], vb[0], vb[1]);
                MMAH16816(o[nf2*2+1], pa[0], pa[1], pa[2], pa[3], vb[2], vb[3]);
            }
        }
    }

    lsum0 += __shfl_xor_sync(0xffffffffu, lsum0, 1);
    lsum0 += __shfl_xor_sync(0xffffffffu, lsum0, 2);
    lsum1 += __shfl_xor_sync(0xffffffffu, lsum1, 1);
    lsum1 += __shfl_xor_sync(0xffffffffu, lsum1, 2);
    const float inv0 = 1.0f / lsum0;
    const float inv1 = 1.0f / lsum1;

    __half* yp0 = g_yf + ((size_t)(b * T_) + row0) * C_ + h * D_ + (lane & 3) * 2;
    __half* yp1 = yp0 + (size_t)8 * C_;
    #pragma unroll
    for (int nf = 0; nf < 8; nf++) {
        *(__half2*)(yp0 + nf * 8) = __floats2half2_rn(o[nf][0] * inv0,
                                                      o[nf][1] * inv0);
        *(__half2*)(yp1 + nf * 8) = __floats2half2_rn(o[nf][2] * inv1,
                                                      o[nf][3] * inv1);
    }
}

// ---------------------------------------------------------------------------
extern "C" void kernel_launch(void* const* d_in, const int* in_sizes, int n_in,
                              void* d_out, int out_size)
{
    (void)in_sizes; (void)n_in; (void)out_size;
    const float* x    = (const float*)d_in[0];
    const int*   spl  = (const int*)  d_in[1];
    const float* Wqkv = (const float*)d_in[2];
    const float* bqkv = (const float*)d_in[3];
    const float* Wprj = (const float*)d_in[4];
    const float* bprj = (const float*)d_in[5];
    float* out = (float*)d_out;

    cudaFuncSetAttribute(gemm_f16_kernel<0>,
                         cudaFuncAttributeMaxDynamicSharedMemorySize, GSMEM);
    cudaFuncSetAttribute(gemm_f16_kernel<1>,
                         cudaFuncAttributeMaxDynamicSharedMemorySize, GSMEM);

    __half *xf, *wqf, *wpf, *yf;
    cudaGetSymbolAddress((void**)&xf,  g_xf);
    cudaGetSymbolAddress((void**)&wqf, g_wqf);
    cudaGetSymbolAddress((void**)&wpf, g_wpf);
    cudaGetSymbolAddress((void**)&yf,  g_yf);

    // 0) convert inputs to fp16
    cvt_f16<<<(B_*T_*C_/4 + 255)/256, 256>>>(x, xf, B_*T_*C_/4);
    cvt_f16<<<(3*C_*C_/4 + 255)/256, 256>>>(Wqkv, wqf, 3*C_*C_/4);
    cvt_f16<<<(C_*C_/4 + 255)/256, 256>>>(Wprj, wpf, C_*C_/4);

    // 1) QKV projection (fp16 HMMA, 256x128 tiles, BK=64) -> g_Qf/g_Kf/g_Vf
    gemm_f16_kernel<0><<<dim3(3*C_/128, B_*T_/256), 512, GSMEM>>>(
        xf, wqf, bqkv, nullptr);

    // 2) attention (all-fp16 MMA) -> g_yf
    attn_kernel<<<dim3(T_/128, H_, B_), 256>>>(spl);

    // 3) output projection (fp16 HMMA, 256x128 tiles, BK=64) -> d_out
    gemm_f16_kernel<1><<<dim3(C_/128, B_*T_/256), 512, GSMEM>>>(
        yf, wpf, bprj, out);
}

// round 15
// speedup vs baseline: 1.3002x; 1.0939x over previous
#include <cuda_runtime.h>
#include <cuda_bf16.h>
#include <cuda_fp16.h>
#include <math.h>
#include <stdint.h>

// Problem constants
#define B_ 2
#define T_ 2048
#define C_ 1024
#define H_ 16
#define D_ 64
#define WIN_ 512
#define K_ 1024

// GEMM tiling: CTA 256(M)x128(N), fp16, BK=64/stage (4x K16), 3-stage ring
#define SP 24                        // padded row stride per K16 tile (fp16) = 48 B
#define TILE_A_B (256 * SP * 2)      // 12288 B per 256x16 A tile
#define TILE_B_B (128 * SP * 2)      // 6144 B per 128x16 B tile
#define STAGE_B (4 * (TILE_A_B + TILE_B_B))   // 73728 B
#define NSTAGE 3
#define GSMEM (NSTAGE * STAGE_B)     // 221184 B, 1 CTA/SM

// Attention smem: Qf[128*ASP] + 2 KV buffers of (K 64*ASP + V 64*ASP)
#define ASP 72
#define KV_BUF_H (128 * ASP)               // halves per KV buffer (K+V)
#define ATTN_SMEM ((128 * ASP + 2 * KV_BUF_H) * 2)   // 55296 B

// ---------------- scratch (allocation-free) ----------------
__device__ __half g_Qf[B_*H_*T_*D_];
__device__ __half g_Kf[B_*H_*T_*D_];
__device__ __half g_Vf[B_*H_*T_*D_];
__device__ __half g_xf[B_*T_*C_];
__device__ __half g_wqf[3*C_*C_];
__device__ __half g_wpf[C_*C_];
__device__ __half g_yf[B_*T_*C_];

__device__ __forceinline__ uint32_t smem_u32(const void* p) {
    uint32_t a;
    asm("{ .reg .u64 t; cvta.to.shared.u64 t, %1; cvt.u32.u64 %0, t; }"
        : "=r"(a) : "l"(p));
    return a;
}
#define LDMX4(r0, r1, r2, r3, addr)                                          \
    asm volatile("ldmatrix.sync.aligned.m8n8.x4.shared.b16 {%0,%1,%2,%3}, [%4];" \
        : "=r"(r0), "=r"(r1), "=r"(r2), "=r"(r3) : "r"(addr))
#define LDMX4T(r0, r1, r2, r3, addr)                                         \
    asm volatile("ldmatrix.sync.aligned.m8n8.x4.trans.shared.b16 {%0,%1,%2,%3}, [%4];" \
        : "=r"(r0), "=r"(r1), "=r"(r2), "=r"(r3) : "r"(addr))
// fp16 HMMA
#define MMAH16816(c, a0, a1, a2, a3, b0, b1)                                 \
    asm volatile("mma.sync.aligned.m16n8k16.row.col.f32.f16.f16.f32 "        \
        "{%0,%1,%2,%3}, {%4,%5,%6,%7}, {%8,%9}, {%0,%1,%2,%3};"              \
        : "+f"((c)[0]), "+f"((c)[1]), "+f"((c)[2]), "+f"((c)[3])             \
        : "r"(a0), "r"(a1), "r"(a2), "r"(a3), "r"(b0), "r"(b1))
#define CP16(dst, src)                                                       \
    asm volatile("cp.async.cg.shared.global [%0], [%1], 16;" :: "r"(dst), "l"(src))
#define CP_COMMIT() asm volatile("cp.async.commit_group;" ::: "memory")
#define CP_WAIT(n)  asm volatile("cp.async.wait_group %0;" :: "n"(n) : "memory")

__device__ __forceinline__ uint32_t packh2(float a, float b) {
    __half2 h = __floats2half2_rn(a, b);
    return *(uint32_t*)&h;
}

// ---------------- fused fp32->fp16 convert for x, Wqkv, Wproj -------------
#define N4_X  (B_*T_*C_/4)       // 1048576
#define N4_WQ (3*C_*C_/4)        // 786432
#define N4_WP (C_*C_/4)          // 262144
__global__ __launch_bounds__(256) void cvt_all(
    const float* __restrict__ x, const float* __restrict__ wq,
    const float* __restrict__ wp)
{
    int i = blockIdx.x * 256 + threadIdx.x;
    const float* s;
    __half* d;
    if (i < N4_X)                { s = x;  d = g_xf; }
    else if (i < N4_X + N4_WQ)   { s = wq; d = g_wqf; i -= N4_X; }
    else if (i < N4_X + N4_WQ + N4_WP) { s = wp; d = g_wpf; i -= N4_X + N4_WQ; }
    else return;
    float4 v = ((const float4*)s)[i];
    ((__half2*)d)[2*i]   = __floats2half2_rn(v.x, v.y);
    ((__half2*)d)[2*i+1] = __floats2half2_rn(v.z, v.w);
}

// ---------------- fp16 tensor-core GEMM, CTA 256x128, BK=64 (r14) ---------
template <int MODE>
__global__ __launch_bounds__(512, 1) void gemm_f16_kernel(
    const __half* __restrict__ Af, const __half* __restrict__ Bf,
    const float* __restrict__ bias, float* __restrict__ Cout)
{
    extern __shared__ char smem[];
    const uint32_t sb = smem_u32(smem);
    const int tid = threadIdx.x;
    const int wid = tid >> 5;
    const int lane = tid & 31;
    const int warp_m = wid & 3;
    const int warp_n = wid >> 2;
    const int bn = blockIdx.x, bm = blockIdx.y;

    uint32_t cdst[6];
    const __half* csrc6[6];
    #pragma unroll
    for (int i = 0; i < 6; i++) {
        const int c = tid + i * 512;
        const bool isA = c < 2048;
        const int cc = isA ? c : c - 2048;
        const int row = cc >> 3, j = cc & 7;
        const int sub = j >> 1;
        cdst[i] = (isA ? (uint32_t)(sub * TILE_A_B)
                       : (uint32_t)(4 * TILE_A_B + sub * TILE_B_B))
                  + (uint32_t)(row * SP * 2 + (j & 1) * 16);
        csrc6[i] = (isA ? Af + (size_t)(bm * 256 + row) * K_
                        : Bf + (size_t)(bn * 128 + row) * K_) + j * 8;
    }

    const uint32_t aoff = (uint32_t)(
        (warp_m * 64 + (lane & 7) + ((lane >> 3) & 1) * 8) * SP
        + (lane >> 4) * 8) * 2;
    const uint32_t boff = (uint32_t)(
        (warp_n * 32 + (lane & 7) + (lane >> 4) * 8) * SP
        + ((lane >> 3) & 1) * 8) * 2;

    float acc[4][4][4];
    #pragma unroll
    for (int i = 0; i < 4; i++)
        #pragma unroll
        for (int j = 0; j < 4; j++)
            #pragma unroll
            for (int c = 0; c < 4; c++) acc[i][j][c] = 0.f;

    const int NT = K_ / 64;

    #pragma unroll
    for (int st = 0; st < NSTAGE - 1; st++) {
        #pragma unroll
        for (int i = 0; i < 6; i++)
            CP16(sb + st * STAGE_B + cdst[i], csrc6[i] + st * 64);
        CP_COMMIT();
    }

    int cs = 0, pf = 2;
    for (int it = 0; it < NT; ++it) {
        CP_WAIT(1);
        __syncthreads();
        const uint32_t tb = sb + (uint32_t)cs * STAGE_B;

        if (it + 2 < NT) {
            const uint32_t db = sb + (uint32_t)pf * STAGE_B;
            #pragma unroll
            for (int i = 0; i < 6; i++)
                CP16(db + cdst[i], csrc6[i] + (it + 2) * 64);
        }
        CP_COMMIT();

        #pragma unroll
        for (int sub = 0; sub < 4; sub++) {
            const uint32_t ta  = tb + sub * TILE_A_B;
            const uint32_t tbb = tb + 4 * TILE_A_B + sub * TILE_B_B;
            uint32_t af[4][4];
            #pragma unroll
            for (int mf = 0; mf < 4; mf++) {
                const uint32_t ao = ta + aoff + (uint32_t)(mf * 16 * SP) * 2;
                LDMX4(af[mf][0], af[mf][1], af[mf][2], af[mf][3], ao);
            }
            #pragma unroll
            for (int nf2 = 0; nf2 < 2; nf2++) {
                uint32_t bf[4];
                const uint32_t bo = tbb + boff + (uint32_t)(nf2 * 16 * SP) * 2;
                LDMX4(bf[0], bf[1], bf[2], bf[3], bo);
                #pragma unroll
                for (int mf = 0; mf < 4; mf++) {
                    MMAH16816(acc[mf][nf2*2],   af[mf][0], af[mf][1], af[mf][2], af[mf][3],
                              bf[0], bf[1]);
                    MMAH16816(acc[mf][nf2*2+1], af[mf][0], af[mf][1], af[mf][2], af[mf][3],
                              bf[2], bf[3]);
                }
            }
        }
        cs = (cs == 2) ? 0 : cs + 1;
        pf = (pf == 2) ? 0 : pf + 1;
    }
    CP_WAIT(0);

    const int g = lane >> 2, tg = lane & 3;
    #pragma unroll
    for (int mf = 0; mf < 4; mf++) {
        #pragma unroll
        for (int nf = 0; nf < 4; nf++) {
            const int gc = bn * 128 + warp_n * 32 + nf * 8 + tg * 2;
            const float b0 = bias[gc], b1 = bias[gc + 1];
            const int r0 = bm * 256 + warp_m * 64 + mf * 16 + g;
            const float v0 = acc[mf][nf][0] + b0, v1 = acc[mf][nf][1] + b1;
            const float v2 = acc[mf][nf][2] + b0, v3 = acc[mf][nf][3] + b1;
            if (MODE == 0) {
                const int sel = gc >> 10;
                const int within = gc & 1023;
                const int h = within >> 6;
                const int dd = within & 63;
                __half* dst = (sel == 0) ? g_Qf : ((sel == 1) ? g_Kf : g_Vf);
                #pragma unroll
                for (int rr = 0; rr < 2; rr++) {
                    const int m = r0 + rr * 8;
                    const int b = m >> 11, t = m & 2047;
                    const size_t o = (((size_t)(b * H_ + h)) * T_ + t) * D_ + dd;
                    *(__half2*)(dst + o) = __floats2half2_rn(rr ? v2 : v0,
                                                             rr ? v3 : v1);
                }
            } else {
                #pragma unroll
                for (int rr = 0; rr < 2; rr++) {
                    const int m = r0 + rr * 8;
                    float2 y;
                    y.x = rr ? v2 : v0;
                    y.y = rr ? v3 : v1;
                    *(float2*)(Cout + (size_t)m * C_ + gc) = y;
                }
            }
        }
    }
}

// ---------------------------------------------------------------------------
// Polynomial softcap+exp, ONE MUFU per element.
// ---------------------------------------------------------------------------
__device__ __forceinline__ float softp(float raw, bool valid) {
    const float r = fminf(fmaxf(raw, -60.0f), 60.0f);
    const float w = r * r;
    const float u = r * fmaf(fmaf(7.2473e-12f, w, -1.0436162e-6f), w,
                             0.18033688011f);
    float p;
    asm("ex2.approx.f32 %0, %1;" : "=f"(p) : "f"(u));
    return valid ? p : 0.0f;
}

__device__ __forceinline__ bool tile_valid(int kt, int q0, int P) {
    const int k0 = kt * 64;
    return (k0 < P) || ((k0 <= q0 + 127) && (k0 + 63 >= q0 - WIN_));
}

// ---------------------------------------------------------------------------
// Attention: 128 q-rows/CTA, 8 warps, 64-key tiles, all-fp16 MMA.
// K/V double-buffered via cp.async: prefetch next VALID tile during compute.
// One __syncthreads per tile.
// ---------------------------------------------------------------------------
__global__ __launch_bounds__(256, 2) void attn_kernel(const int* __restrict__ spl)
{
    extern __shared__ __half asm_[];
    __half* Qf  = asm_;                       // [128*ASP]
    __half* KV0 = Qf + 128 * ASP;             // buf0: K[64*ASP] + V[64*ASP]

    const int tid = threadIdx.x;
    const int wid = tid >> 5;
    const int lane = tid & 31;
    const int q0 = blockIdx.x * 128;
    const int h = blockIdx.y;
    const int b = blockIdx.z;
    const size_t bh = (size_t)(b * H_ + h) * T_;
    const int P = spl[b];

    // load Q (direct; once)
    for (int i = tid; i < 1024; i += 256) {
        const int r = i >> 3;
        const int c8 = i & 7;
        *(uint4*)(Qf + r * ASP + c8 * 8) =
            *(const uint4*)(g_Qf + (bh + q0 + r) * D_ + c8 * 8);
    }

    // per-thread cp.async chunk map (4 chunks: K 512 + V 512 over 256 threads)
    const uint32_t kv_sb = smem_u32(KV0);

    // fragment base addresses (relative to buffer 0)
    const int a_row = wid * 16 + (lane & 7) + ((lane >> 3) & 1) * 8;
    const int a_kg = (lane >> 4) * 8;
    const uint32_t qf_a = smem_u32(Qf + a_row * ASP + a_kg);
    const int k_row = (lane & 7) + (lane >> 4) * 8;
    const int k_col = ((lane >> 3) & 1) * 8;
    const uint32_t kf_a0 = kv_sb + (uint32_t)(k_row * ASP + k_col) * 2;
    const int v_row = ((lane >> 3) & 1) * 8 + (lane & 7);
    const int v_col = (lane >> 4) * 8;
    const uint32_t vf_a0 = kv_sb + (uint32_t)(64 * ASP + v_row * ASP + v_col) * 2;

    float o[8][4];
    #pragma unroll
    for (int i = 0; i < 8; i++)
        #pragma unroll
        for (int j = 0; j < 4; j++) o[i][j] = 0.f;
    float lsum0 = 0.f, lsum1 = 0.f;
    const int row0 = q0 + wid * 16 + (lane >> 2);

    // issue loads for tile kt into buffer bsel
    auto issue_load = [&](int kt, int bsel) {
        #pragma unroll
        for (int j = 0; j < 4; j++) {
            const int c = tid + j * 256;
            const int arr = c >> 9;              // 0=K 1=V
            const int r = (c >> 3) & 63;
            const int c8 = c & 7;
            const __half* src = (arr ? g_Vf : g_Kf) + (bh + kt * 64 + r) * D_ + c8 * 8;
            const uint32_t dst = kv_sb + (uint32_t)(bsel * KV_BUF_H) * 2
                               + (uint32_t)(arr * 64 * ASP + r * ASP + c8 * 8) * 2;
            CP16(dst, src);
        }
    };

    // first valid tile
    int kt = 0;
    while (kt < T_ / 64 && !tile_valid(kt, q0, P)) kt++;
    if (kt < T_ / 64) issue_load(kt, 0);
    CP_COMMIT();

    int buf = 0;
    __syncthreads();   // Q tile visible (and aligns with first wait)

    while (kt < T_ / 64) {
        int nkt = kt + 1;
        while (nkt < T_ / 64 && !tile_valid(nkt, q0, P)) nkt++;

        CP_WAIT(0);
        __syncthreads();           // tile kt resident & visible to all warps
        if (nkt < T_ / 64) issue_load(nkt, buf ^ 1);
        CP_COMMIT();               // uniform group count

        const uint32_t kf_a = kf_a0 + (uint32_t)(buf * KV_BUF_H) * 2;
        const uint32_t vf_a = vf_a0 + (uint32_t)(buf * KV_BUF_H) * 2;
        const int k0 = kt * 64;

        // ---- QK^T ----
        float s[8][4];
        #pragma unroll
        for (int i = 0; i < 8; i++)
            #pragma unroll
            for (int j = 0; j < 4; j++) s[i][j] = 0.f;

        #pragma unroll
        for (int kk4 = 0; kk4 < 4; kk4++) {
            uint32_t qa[4];
            LDMX4(qa[0], qa[1], qa[2], qa[3], qf_a + kk4 * 32);
            #pragma unroll
            for (int nf2 = 0; nf2 < 4; nf2++) {
                uint32_t kb[4];
                LDMX4(kb[0], kb[1], kb[2], kb[3],
                      kf_a + (uint32_t)(nf2 * 16 * ASP) * 2 + kk4 * 32);
                MMAH16816(s[nf2*2],   qa[0], qa[1], qa[2], qa[3], kb[0], kb[1]);
                MMAH16816(s[nf2*2+1], qa[0], qa[1], qa[2], qa[3], kb[2], kb[3]);
            }
        }

        // ---- softcap/mask/exp + repack + PV ----
        #pragma unroll
        for (int kc = 0; kc < 4; kc++) {
            uint32_t pa[4];
            #pragma unroll
            for (int j = 0; j < 2; j++) {
                const int nf = kc * 2 + j;
                const int cb = k0 + nf * 8 + (lane & 3) * 2;
                const bool va0 = ((cb     <= row0)     && (row0     - cb     <= WIN_)) || (cb     < P);
                const bool va1 = ((cb + 1 <= row0)     && (row0     - cb - 1 <= WIN_)) || (cb + 1 < P);
                const bool va2 = ((cb     <= row0 + 8) && (row0 + 8 - cb     <= WIN_)) || (cb     < P);
                const bool va3 = ((cb + 1 <= row0 + 8) && (row0 + 8 - cb - 1 <= WIN_)) || (cb + 1 < P);
                const float p0 = softp(s[nf][0], va0);
                const float p1 = softp(s[nf][1], va1);
                const float p2 = softp(s[nf][2], va2);
                const float p3 = softp(s[nf][3], va3);
                lsum0 += p0 + p1;
                lsum1 += p2 + p3;
                pa[j*2]   = packh2(p0, p1);
                pa[j*2+1] = packh2(p2, p3);
            }
            #pragma unroll
            for (int nf2 = 0; nf2 < 4; nf2++) {
                uint32_t vb[4];
                const uint32_t off = (uint32_t)(kc * 16 * ASP + nf2 * 16) * 2;
                LDMX4T(vb[0], vb[1], vb[2], vb[3], vf_a + off);
                MMAH16816(o[nf2*2],   pa[0], pa[1], pa[2], pa[3], vb[0], vb[1]);
                MMAH16816(o[nf2*2+1], pa[0], pa[1], pa[2], pa[3], vb[2], vb[3]);
            }
        }

        buf ^= 1;
        kt = nkt;
    }

    lsum0 += __shfl_xor_sync(0xffffffffu, lsum0, 1);
    lsum0 += __shfl_xor_sync(0xffffffffu, lsum0, 2);
    lsum1 += __shfl_xor_sync(0xffffffffu, lsum1, 1);
    lsum1 += __shfl_xor_sync(0xffffffffu, lsum1, 2);
    const float inv0 = 1.0f / lsum0;
    const float inv1 = 1.0f / lsum1;

    __half* yp0 = g_yf + ((size_t)(b * T_) + row0) * C_ + h * D_ + (lane & 3) * 2;
    __half* yp1 = yp0 + (size_t)8 * C_;
    #pragma unroll
    for (int nf = 0; nf < 8; nf++) {
        *(__half2*)(yp0 + nf * 8) = __floats2half2_rn(o[nf][0] * inv0,
                                                      o[nf][1] * inv0);
        *(__half2*)(yp1 + nf * 8) = __floats2half2_rn(o[nf][2] * inv1,
                                                      o[nf][3] * inv1);
    }
}

// ---------------------------------------------------------------------------
extern "C" void kernel_launch(void* const* d_in, const int* in_sizes, int n_in,
                              void* d_out, int out_size)
{
    (void)in_sizes; (void)n_in; (void)out_size;
    const float* x    = (const float*)d_in[0];
    const int*   spl  = (const int*)  d_in[1];
    const float* Wqkv = (const float*)d_in[2];
    const float* bqkv = (const float*)d_in[3];
    const float* Wprj = (const float*)d_in[4];
    const float* bprj = (const float*)d_in[5];
    float* out = (float*)d_out;

    cudaFuncSetAttribute(gemm_f16_kernel<0>,
                         cudaFuncAttributeMaxDynamicSharedMemorySize, GSMEM);
    cudaFuncSetAttribute(gemm_f16_kernel<1>,
                         cudaFuncAttributeMaxDynamicSharedMemorySize, GSMEM);
    cudaFuncSetAttribute(attn_kernel,
                         cudaFuncAttributeMaxDynamicSharedMemorySize, ATTN_SMEM);

    __half *xf, *wqf, *wpf, *yf;
    cudaGetSymbolAddress((void**)&xf,  g_xf);
    cudaGetSymbolAddress((void**)&wqf, g_wqf);
    cudaGetSymbolAddress((void**)&wpf, g_wpf);
    cudaGetSymbolAddress((void**)&yf,  g_yf);

    // 0) fused fp32->fp16 conversion of x, Wqkv, Wproj (single launch)
    const int n4_total = N4_X + N4_WQ + N4_WP;
    cvt_all<<<(n4_total + 255) / 256, 256>>>(x, Wqkv, Wprj);

    // 1) QKV projection (fp16 HMMA, 256x128, BK=64) -> g_Qf/g_Kf/g_Vf
    gemm_f16_kernel<0><<<dim3(3*C_/128, B_*T_/256), 512, GSMEM>>>(
        xf, wqf, bqkv, nullptr);

    // 2) attention (fp16 MMA, cp.async double-buffered K/V) -> g_yf
    attn_kernel<<<dim3(T_/128, H_, B_), 256, ATTN_SMEM>>>(spl);

    // 3) output projection (fp16 HMMA, 256x128, BK=64) -> d_out
    gemm_f16_kernel<1><<<dim3(C_/128, B_*T_/256), 512, GSMEM>>>(
        yf, wpf, bprj, out);
}